// round 1
// baseline (speedup 1.0000x reference)
#include <cuda_runtime.h>
#include <math.h>

#define MROWS 32768
#define DMODEL 512
#define FFND 2048
#define APAD 68

// ---------------- scratch (static device allocations; allowed) ----------------
__device__ float g_hn[(size_t)MROWS * DMODEL];
__device__ float g_q [(size_t)MROWS * DMODEL];
__device__ float g_k [(size_t)MROWS * DMODEL];
__device__ float g_v [(size_t)MROWS * DMODEL];
__device__ float g_o [(size_t)MROWS * DMODEL];
__device__ float g_h [(size_t)MROWS * DMODEL];
__device__ float g_ff[(size_t)MROWS * FFND];

// ---------------- LayerNorm: one block per row (512 cols, 256 thr) ----------------
__global__ void ln_kernel(const float* __restrict__ x, const float* __restrict__ g,
                          const float* __restrict__ b, float* __restrict__ y) {
    int row = blockIdx.x;
    int tid = threadIdx.x;
    const float2* xr = (const float2*)(x + (size_t)row * DMODEL);
    float2 v = xr[tid];
    float s  = v.x + v.y;
    float ss = v.x * v.x + v.y * v.y;
    #pragma unroll
    for (int o = 16; o > 0; o >>= 1) {
        s  += __shfl_xor_sync(0xffffffffu, s,  o);
        ss += __shfl_xor_sync(0xffffffffu, ss, o);
    }
    __shared__ float sh[16];
    int w = tid >> 5, lane = tid & 31;
    if (lane == 0) { sh[w] = s; sh[8 + w] = ss; }
    __syncthreads();
    if (tid == 0) {
        float ts = 0.f, tss = 0.f;
        #pragma unroll
        for (int i = 0; i < 8; i++) { ts += sh[i]; tss += sh[8 + i]; }
        sh[0] = ts; sh[8] = tss;
    }
    __syncthreads();
    float mean = sh[0] * (1.0f / DMODEL);
    float var  = sh[8] * (1.0f / DMODEL) - mean * mean;
    float rstd = rsqrtf(var + 1e-5f);
    float2 gg = ((const float2*)g)[tid];
    float2 bb = ((const float2*)b)[tid];
    float2 o2;
    o2.x = (v.x - mean) * rstd * gg.x + bb.x;
    o2.y = (v.y - mean) * rstd * gg.y + bb.y;
    ((float2*)(y + (size_t)row * DMODEL))[tid] = o2;
}

// ---------------- SGEMM: C = epilogue(A[MxK] @ B[KxN] + bias) ----------------
// 128x128 tile, BK=16, 256 threads, 8x8 micro-tile (split 4+4 rows/cols), reg prefetch.
__global__ __launch_bounds__(256) void gemm_kernel(
    const float* __restrict__ A, const float* __restrict__ B,
    const float* __restrict__ bias, const float* __restrict__ res,
    float* __restrict__ C, int M, int N, int K, float scale, int do_gelu)
{
    __shared__ float As[16][128];
    __shared__ float Bs[16][128];
    int tid = threadIdx.x;
    int tx = tid & 15, ty = tid >> 4;
    int bm = blockIdx.y * 128, bn = blockIdx.x * 128;

    float4 apre[2], bpre[2];
    #pragma unroll
    for (int l = 0; l < 2; l++) {
        int f = tid + l * 256;
        apre[l] = *(const float4*)(A + (size_t)(bm + (f >> 2)) * K + ((f & 3) << 2));
        bpre[l] = *(const float4*)(B + (size_t)(f >> 5) * N + bn + ((f & 31) << 2));
    }

    float acc[8][8];
    #pragma unroll
    for (int i = 0; i < 8; i++)
        #pragma unroll
        for (int j = 0; j < 8; j++) acc[i][j] = 0.f;

    for (int kt = 0; kt < K; kt += 16) {
        __syncthreads();
        #pragma unroll
        for (int l = 0; l < 2; l++) {
            int f = tid + l * 256;
            int arow = f >> 2, ak = (f & 3) << 2;
            As[ak + 0][arow] = apre[l].x;
            As[ak + 1][arow] = apre[l].y;
            As[ak + 2][arow] = apre[l].z;
            As[ak + 3][arow] = apre[l].w;
            *(float4*)&Bs[f >> 5][(f & 31) << 2] = bpre[l];
        }
        __syncthreads();
        if (kt + 16 < K) {
            #pragma unroll
            for (int l = 0; l < 2; l++) {
                int f = tid + l * 256;
                apre[l] = *(const float4*)(A + (size_t)(bm + (f >> 2)) * K + kt + 16 + ((f & 3) << 2));
                bpre[l] = *(const float4*)(B + (size_t)(kt + 16 + (f >> 5)) * N + bn + ((f & 31) << 2));
            }
        }
        #pragma unroll
        for (int kk = 0; kk < 16; kk++) {
            float af[8], bf[8];
            *(float4*)&af[0] = *(const float4*)&As[kk][ty << 2];
            *(float4*)&af[4] = *(const float4*)&As[kk][(ty << 2) + 64];
            *(float4*)&bf[0] = *(const float4*)&Bs[kk][tx << 2];
            *(float4*)&bf[4] = *(const float4*)&Bs[kk][(tx << 2) + 64];
            #pragma unroll
            for (int i = 0; i < 8; i++)
                #pragma unroll
                for (int j = 0; j < 8; j++)
                    acc[i][j] = fmaf(af[i], bf[j], acc[i][j]);
        }
    }

    #pragma unroll
    for (int ih = 0; ih < 2; ih++)
        #pragma unroll
        for (int i = 0; i < 4; i++) {
            size_t row = (size_t)bm + ih * 64 + (ty << 2) + i;
            #pragma unroll
            for (int jh = 0; jh < 2; jh++) {
                int col = bn + jh * 64 + (tx << 2);
                float vv[4];
                #pragma unroll
                for (int j = 0; j < 4; j++) {
                    float val = (acc[ih * 4 + i][jh * 4 + j] + bias[col + j]) * scale;
                    if (do_gelu) val = 0.5f * val * (1.0f + erff(val * 0.7071067811865475f));
                    if (res) val += res[row * (size_t)N + col + j];
                    vv[j] = val;
                }
                *(float4*)&C[row * (size_t)N + col] = *(float4*)vv;
            }
        }
}

// ---------------- RoPE (in-place on q and k; only first 16 of 32 pairs rotate) ----------------
__global__ void rope_kernel(float* __restrict__ q, float* __restrict__ k) {
    int i = blockIdx.x * 256 + threadIdx.x;     // 2^23 items
    int j   = i & 15;
    int h   = (i >> 4) & 7;
    int row = (i >> 7) & (MROWS - 1);
    float* base = (i >> 22) ? k : q;
    int s = row & 511;
    // inv_timescale = 10000^{-j/32} = exp(-j * ln(10000)/32)
    float ang = (float)s * expf(-(float)j * 0.28782313662425575f);
    float sn, cs;
    sincosf(ang, &sn, &cs);
    float* p = base + (size_t)row * DMODEL + h * 64 + j;
    float x1 = p[0], x2 = p[32];
    p[0]  = x1 * cs - x2 * sn;
    p[32] = x2 * cs + x1 * sn;
}

// ---------------- Flash attention: block = (64 q-rows) x one (bc,h); 8 k-tiles of 64 ----------------
__global__ __launch_bounds__(256) void attn_kernel(
    const float* __restrict__ q, const float* __restrict__ k,
    const float* __restrict__ v, float* __restrict__ o)
{
    extern __shared__ float smf[];
    float* Qs = smf;
    float* Ks = smf + 64 * APAD;
    float* Vs = smf + 2 * 64 * APAD;
    float* Ps = smf + 3 * 64 * APAD;

    int qt = blockIdx.x, bch = blockIdx.y;
    int bc = bch >> 3, h = bch & 7;
    int tid = threadIdx.x;
    int tx = tid & 15, ty = tid >> 4;

    const float* qb = q + (size_t)(bc * 512 + qt * 64) * 512 + h * 64;
    const float* kb = k + (size_t)(bc * 512) * 512 + h * 64;
    const float* vb = v + (size_t)(bc * 512) * 512 + h * 64;

    #pragma unroll
    for (int l = 0; l < 4; l++) {
        int f = tid + l * 256;
        int r = f >> 4, d4 = (f & 15) << 2;
        *(float4*)&Qs[r * APAD + d4] = *(const float4*)(qb + (size_t)r * 512 + d4);
    }

    float4 kreg[4], vreg[4];
    #pragma unroll
    for (int l = 0; l < 4; l++) {
        int f = tid + l * 256;
        int r = f >> 4, d4 = (f & 15) << 2;
        kreg[l] = *(const float4*)(kb + (size_t)r * 512 + d4);
        vreg[l] = *(const float4*)(vb + (size_t)r * 512 + d4);
    }

    float m_[4], l_[4], oacc[4][4];
    #pragma unroll
    for (int i = 0; i < 4; i++) {
        m_[i] = -1e30f; l_[i] = 0.f;
        #pragma unroll
        for (int c = 0; c < 4; c++) oacc[i][c] = 0.f;
    }

    for (int kt = 0; kt < 8; kt++) {
        __syncthreads();   // protects K/V/P from previous iteration's readers
        #pragma unroll
        for (int l = 0; l < 4; l++) {
            int f = tid + l * 256;
            int r = f >> 4, d4 = (f & 15) << 2;
            *(float4*)&Ks[r * APAD + d4] = kreg[l];
            *(float4*)&Vs[r * APAD + d4] = vreg[l];
        }
        __syncthreads();
        if (kt < 7) {
            #pragma unroll
            for (int l = 0; l < 4; l++) {
                int f = tid + l * 256;
                int r = f >> 4, d4 = (f & 15) << 2;
                kreg[l] = *(const float4*)(kb + (size_t)((kt + 1) * 64 + r) * 512 + d4);
                vreg[l] = *(const float4*)(vb + (size_t)((kt + 1) * 64 + r) * 512 + d4);
            }
        }

        // S = Q @ K^T : rows {ty+16*ii}, cols {tx+16*jj}
        float s[4][4];
        #pragma unroll
        for (int a = 0; a < 4; a++)
            #pragma unroll
            for (int b = 0; b < 4; b++) s[a][b] = 0.f;
        #pragma unroll
        for (int d4 = 0; d4 < 64; d4 += 4) {
            float4 qv[4], kv[4];
            #pragma unroll
            for (int ii = 0; ii < 4; ii++) qv[ii] = *(const float4*)&Qs[(ty + 16 * ii) * APAD + d4];
            #pragma unroll
            for (int jj = 0; jj < 4; jj++) kv[jj] = *(const float4*)&Ks[(tx + 16 * jj) * APAD + d4];
            #pragma unroll
            for (int ii = 0; ii < 4; ii++)
                #pragma unroll
                for (int jj = 0; jj < 4; jj++) {
                    s[ii][jj] = fmaf(qv[ii].x, kv[jj].x, s[ii][jj]);
                    s[ii][jj] = fmaf(qv[ii].y, kv[jj].y, s[ii][jj]);
                    s[ii][jj] = fmaf(qv[ii].z, kv[jj].z, s[ii][jj]);
                    s[ii][jj] = fmaf(qv[ii].w, kv[jj].w, s[ii][jj]);
                }
        }

        // online softmax over this tile's 64 cols (16 threads share each row)
        #pragma unroll
        for (int ii = 0; ii < 4; ii++) {
            float rm = fmaxf(fmaxf(s[ii][0], s[ii][1]), fmaxf(s[ii][2], s[ii][3]));
            #pragma unroll
            for (int off = 8; off > 0; off >>= 1)
                rm = fmaxf(rm, __shfl_xor_sync(0xffffffffu, rm, off));
            float mn = fmaxf(m_[ii], rm);
            float corr = __expf(m_[ii] - mn);
            float rs = 0.f;
            #pragma unroll
            for (int jj = 0; jj < 4; jj++) {
                s[ii][jj] = __expf(s[ii][jj] - mn);
                rs += s[ii][jj];
            }
            #pragma unroll
            for (int off = 8; off > 0; off >>= 1)
                rs += __shfl_xor_sync(0xffffffffu, rs, off);
            l_[ii] = l_[ii] * corr + rs;
            m_[ii] = mn;
            #pragma unroll
            for (int cc = 0; cc < 4; cc++) oacc[ii][cc] *= corr;
        }

        // stage P, then O += P @ V
        #pragma unroll
        for (int ii = 0; ii < 4; ii++)
            #pragma unroll
            for (int jj = 0; jj < 4; jj++)
                Ps[(ty + 16 * ii) * APAD + tx + 16 * jj] = s[ii][jj];
        __syncthreads();
        #pragma unroll 4
        for (int j = 0; j < 64; j++) {
            float pv[4], vv[4];
            #pragma unroll
            for (int ii = 0; ii < 4; ii++) pv[ii] = Ps[(ty + 16 * ii) * APAD + j];
            #pragma unroll
            for (int cc = 0; cc < 4; cc++) vv[cc] = Vs[j * APAD + tx + 16 * cc];
            #pragma unroll
            for (int ii = 0; ii < 4; ii++)
                #pragma unroll
                for (int cc = 0; cc < 4; cc++)
                    oacc[ii][cc] = fmaf(pv[ii], vv[cc], oacc[ii][cc]);
        }
    }

    float* ob = o + (size_t)(bc * 512 + qt * 64) * 512 + h * 64;
    #pragma unroll
    for (int ii = 0; ii < 4; ii++) {
        float inv = 1.0f / l_[ii];
        #pragma unroll
        for (int cc = 0; cc < 4; cc++)
            ob[(size_t)(ty + 16 * ii) * 512 + tx + 16 * cc] = oacc[ii][cc] * inv;
    }
}

// ---------------- launch ----------------
extern "C" void kernel_launch(void* const* d_in, const int* in_sizes, int n_in,
                              void* d_out, int out_size) {
    const float* x    = (const float*)d_in[0];
    const float* Wq   = (const float*)d_in[1];
    const float* bq   = (const float*)d_in[2];
    const float* Wk   = (const float*)d_in[3];
    const float* bk   = (const float*)d_in[4];
    const float* Wv   = (const float*)d_in[5];
    const float* bv   = (const float*)d_in[6];
    const float* Wo   = (const float*)d_in[7];
    const float* bo   = (const float*)d_in[8];
    const float* ln1g = (const float*)d_in[9];
    const float* ln1b = (const float*)d_in[10];
    const float* ln3g = (const float*)d_in[11];
    const float* ln3b = (const float*)d_in[12];
    const float* W1   = (const float*)d_in[13];
    const float* b1   = (const float*)d_in[14];
    const float* W2   = (const float*)d_in[15];
    const float* b2   = (const float*)d_in[16];
    float* out = (float*)d_out;

    float *hn, *qp, *kp, *vp, *op, *hp, *ffp;
    cudaGetSymbolAddress((void**)&hn,  g_hn);
    cudaGetSymbolAddress((void**)&qp,  g_q);
    cudaGetSymbolAddress((void**)&kp,  g_k);
    cudaGetSymbolAddress((void**)&vp,  g_v);
    cudaGetSymbolAddress((void**)&op,  g_o);
    cudaGetSymbolAddress((void**)&hp,  g_h);
    cudaGetSymbolAddress((void**)&ffp, g_ff);

    const int smemA = 4 * 64 * APAD * (int)sizeof(float);
    cudaFuncSetAttribute(attn_kernel, cudaFuncAttributeMaxDynamicSharedMemorySize, smemA);

    dim3 gqkv(DMODEL / 128, MROWS / 128);

    // 1. LN1
    ln_kernel<<<MROWS, 256>>>(x, ln1g, ln1b, hn);
    // 2-4. QKV projections (q pre-scaled by HD^-0.5 = 0.125)
    gemm_kernel<<<gqkv, 256>>>(hn, Wq, bq, nullptr, qp, MROWS, DMODEL, DMODEL, 0.125f, 0);
    gemm_kernel<<<gqkv, 256>>>(hn, Wk, bk, nullptr, kp, MROWS, DMODEL, DMODEL, 1.0f, 0);
    gemm_kernel<<<gqkv, 256>>>(hn, Wv, bv, nullptr, vp, MROWS, DMODEL, DMODEL, 1.0f, 0);
    // 5. RoPE on q,k (in place)
    rope_kernel<<<32768, 256>>>(qp, kp);
    // 6. attention
    attn_kernel<<<dim3(8, 512), 256, smemA>>>(qp, kp, vp, op);
    // 7. O-proj + residual(x)
    gemm_kernel<<<gqkv, 256>>>(op, Wo, bo, x, hp, MROWS, DMODEL, DMODEL, 1.0f, 0);
    // 8. LN3
    ln_kernel<<<MROWS, 256>>>(hp, ln3g, ln3b, hn);
    // 9. FFN up + exact GELU
    gemm_kernel<<<dim3(FFND / 128, MROWS / 128), 256>>>(hn, W1, b1, nullptr, ffp, MROWS, FFND, DMODEL, 1.0f, 1);
    // 10. FFN down + bias + residual(h) -> out
    gemm_kernel<<<gqkv, 256>>>(ffp, W2, b2, hp, out, MROWS, DMODEL, FFND, 1.0f, 0);
}

// round 3
// speedup vs baseline: 2.4909x; 2.4909x over previous
#include <cuda_runtime.h>
#include <cuda_fp16.h>
#include <math.h>
#include <stdint.h>

#define MROWS 32768
#define DMODEL 512
#define FFND 2048
#define APAD 68
#define SAPAD 40   // halfs per smem row (32 data + 8 pad)

// ---------------- scratch ----------------
__device__ float g_hn[(size_t)MROWS * DMODEL];
__device__ float g_q [(size_t)MROWS * DMODEL];
__device__ float g_k [(size_t)MROWS * DMODEL];
__device__ float g_v [(size_t)MROWS * DMODEL];
__device__ float g_o [(size_t)MROWS * DMODEL];
__device__ float g_h [(size_t)MROWS * DMODEL];
__device__ float g_ff[(size_t)MROWS * FFND];
__device__ float g_wT[4 * 512 * 512 + 2 * 512 * 2048];   // transposed weights

__device__ __forceinline__ uint32_t smem_u32(const void* p) {
    uint32_t a;
    asm("{ .reg .u64 t; cvta.to.shared.u64 t, %1; cvt.u32.u64 %0, t; }" : "=r"(a) : "l"(p));
    return a;
}

// ---------------- weight transpose (R x C -> C x R) ----------------
__global__ void transpose_kernel(const float* __restrict__ in, float* __restrict__ out,
                                 int R, int C) {
    __shared__ float t[32][33];
    int bc = blockIdx.x * 32, br = blockIdx.y * 32;
    int x = threadIdx.x, y = threadIdx.y;
    #pragma unroll
    for (int i = 0; i < 32; i += 8)
        t[y + i][x] = in[(size_t)(br + y + i) * C + bc + x];
    __syncthreads();
    #pragma unroll
    for (int i = 0; i < 32; i += 8)
        out[(size_t)(bc + y + i) * R + br + x] = t[x][y + i];
}

// ---------------- LayerNorm ----------------
__global__ void ln_kernel(const float* __restrict__ x, const float* __restrict__ g,
                          const float* __restrict__ b, float* __restrict__ y) {
    int row = blockIdx.x;
    int tid = threadIdx.x;
    const float2* xr = (const float2*)(x + (size_t)row * DMODEL);
    float2 v = xr[tid];
    float s  = v.x + v.y;
    float ss = v.x * v.x + v.y * v.y;
    #pragma unroll
    for (int o = 16; o > 0; o >>= 1) {
        s  += __shfl_xor_sync(0xffffffffu, s,  o);
        ss += __shfl_xor_sync(0xffffffffu, ss, o);
    }
    __shared__ float sh[16];
    int w = tid >> 5, lane = tid & 31;
    if (lane == 0) { sh[w] = s; sh[8 + w] = ss; }
    __syncthreads();
    if (tid == 0) {
        float ts = 0.f, tss = 0.f;
        #pragma unroll
        for (int i = 0; i < 8; i++) { ts += sh[i]; tss += sh[8 + i]; }
        sh[0] = ts; sh[8] = tss;
    }
    __syncthreads();
    float mean = sh[0] * (1.0f / DMODEL);
    float var  = sh[8] * (1.0f / DMODEL) - mean * mean;
    float rstd = rsqrtf(var + 1e-5f);
    float2 gg = ((const float2*)g)[tid];
    float2 bb = ((const float2*)b)[tid];
    float2 o2;
    o2.x = (v.x - mean) * rstd * gg.x + bb.x;
    o2.y = (v.y - mean) * rstd * gg.y + bb.y;
    ((float2*)(y + (size_t)row * DMODEL))[tid] = o2;
}

// ---------------- HMMA fp16 GEMM: C = epi(A[MxK] @ Bt[NxK]^T) ----------------
// 128x128 CTA tile, BK=32, 256 thr, 8 warps (2m x 4n), warp tile 64x32.
__global__ __launch_bounds__(256) void mma_gemm(
    const float* __restrict__ A, const float* __restrict__ Bt,
    const float* __restrict__ bias, const float* __restrict__ res,
    float* __restrict__ C, int M, int N, int K, float scale, int do_gelu)
{
    // smem: stage s: A at s*10240, B at s*10240+5120 (in halfs). 40960 B total.
    __shared__ __half sm[20480];
    uint32_t smb = smem_u32(sm);

    int tid = threadIdx.x;
    int wid = tid >> 5, lane = tid & 31;
    int bm = blockIdx.y * 128, bn = blockIdx.x * 128;
    int wm = (wid >> 2) * 64, wn = (wid & 3) * 32;

    const float* Ab = A  + (size_t)bm * K;
    const float* Bb = Bt + (size_t)bn * K;

    int lrow = tid >> 1;            // 0..127
    int lko  = (tid & 1) * 16;      // 0 or 16

    // fragment ldmatrix addresses (lane-dependent, in half units)
    // A: rows wm + mi*16 + (lane&15), k = kb + (lane>>4)*8
    uint32_t a_lrow = (uint32_t)(wm + (lane & 15));
    uint32_t a_lk   = (uint32_t)((lane >> 4) * 8);
    // B: rows wn + nhalf*16 + (lane>>4)*8 + (lane&7), k = kb + ((lane>>3)&1)*8
    uint32_t b_lrow = (uint32_t)(wn + ((lane >> 4) << 3) + (lane & 7));
    uint32_t b_lk   = (uint32_t)(((lane >> 3) & 1) * 8);

    float acc[4][4][4];
    #pragma unroll
    for (int i = 0; i < 4; i++)
        #pragma unroll
        for (int j = 0; j < 4; j++)
            #pragma unroll
            for (int c = 0; c < 4; c++) acc[i][j][c] = 0.f;

    float4 ar[4], br[4];
    #pragma unroll
    for (int l = 0; l < 4; l++) {
        ar[l] = *(const float4*)(Ab + (size_t)lrow * K + lko + (l << 2));
        br[l] = *(const float4*)(Bb + (size_t)lrow * K + lko + (l << 2));
    }

    int nch = K >> 5;
    for (int ch = 0; ch < nch; ch++) {
        int sbase = (ch & 1) * 10240;
        __syncthreads();
        // convert + STS
        {
            union { __half2 h2[4]; uint4 u; } pa, pb;
            int off = sbase + lrow * SAPAD + lko;
            #pragma unroll
            for (int hh = 0; hh < 2; hh++) {
                pa.h2[0] = __floats2half2_rn(ar[hh*2].x, ar[hh*2].y);
                pa.h2[1] = __floats2half2_rn(ar[hh*2].z, ar[hh*2].w);
                pa.h2[2] = __floats2half2_rn(ar[hh*2+1].x, ar[hh*2+1].y);
                pa.h2[3] = __floats2half2_rn(ar[hh*2+1].z, ar[hh*2+1].w);
                *(uint4*)(&sm[off + hh * 8]) = pa.u;
                pb.h2[0] = __floats2half2_rn(br[hh*2].x, br[hh*2].y);
                pb.h2[1] = __floats2half2_rn(br[hh*2].z, br[hh*2].w);
                pb.h2[2] = __floats2half2_rn(br[hh*2+1].x, br[hh*2+1].y);
                pb.h2[3] = __floats2half2_rn(br[hh*2+1].z, br[hh*2+1].w);
                *(uint4*)(&sm[5120 + off + hh * 8]) = pb.u;
            }
        }
        __syncthreads();
        // prefetch next chunk
        if (ch + 1 < nch) {
            int kc = (ch + 1) << 5;
            #pragma unroll
            for (int l = 0; l < 4; l++) {
                ar[l] = *(const float4*)(Ab + (size_t)lrow * K + kc + lko + (l << 2));
                br[l] = *(const float4*)(Bb + (size_t)lrow * K + kc + lko + (l << 2));
            }
        }
        // compute: 2 k16 steps
        uint32_t abase = smb + (uint32_t)sbase * 2;
        uint32_t bbase = abase + 10240u;
        #pragma unroll
        for (int ks = 0; ks < 2; ks++) {
            uint32_t kb = (uint32_t)(ks << 4);
            uint32_t afr[4][4], bfr[2][4];
            #pragma unroll
            for (int mi = 0; mi < 4; mi++) {
                uint32_t addr = abase + ((a_lrow + mi * 16) * SAPAD + kb + a_lk) * 2;
                asm volatile("ldmatrix.sync.aligned.m8n8.x4.shared.b16 {%0,%1,%2,%3}, [%4];"
                    : "=r"(afr[mi][0]), "=r"(afr[mi][1]), "=r"(afr[mi][2]), "=r"(afr[mi][3])
                    : "r"(addr));
            }
            #pragma unroll
            for (int nh = 0; nh < 2; nh++) {
                uint32_t addr = bbase + ((b_lrow + nh * 16) * SAPAD + kb + b_lk) * 2;
                asm volatile("ldmatrix.sync.aligned.m8n8.x4.shared.b16 {%0,%1,%2,%3}, [%4];"
                    : "=r"(bfr[nh][0]), "=r"(bfr[nh][1]), "=r"(bfr[nh][2]), "=r"(bfr[nh][3])
                    : "r"(addr));
            }
            #pragma unroll
            for (int mi = 0; mi < 4; mi++)
                #pragma unroll
                for (int nj = 0; nj < 4; nj++) {
                    uint32_t b0 = bfr[nj >> 1][(nj & 1) * 2];
                    uint32_t b1 = bfr[nj >> 1][(nj & 1) * 2 + 1];
                    asm volatile(
                        "mma.sync.aligned.m16n8k16.row.col.f32.f16.f16.f32 "
                        "{%0,%1,%2,%3}, {%4,%5,%6,%7}, {%8,%9}, {%0,%1,%2,%3};"
                        : "+f"(acc[mi][nj][0]), "+f"(acc[mi][nj][1]),
                          "+f"(acc[mi][nj][2]), "+f"(acc[mi][nj][3])
                        : "r"(afr[mi][0]), "r"(afr[mi][1]), "r"(afr[mi][2]), "r"(afr[mi][3]),
                          "r"(b0), "r"(b1));
                }
        }
    }

    // epilogue
    int g4 = lane >> 2, tc = (lane & 3) * 2;
    #pragma unroll
    for (int mi = 0; mi < 4; mi++) {
        #pragma unroll
        for (int r = 0; r < 2; r++) {
            size_t row = (size_t)(bm + wm + mi * 16 + g4 + r * 8);
            #pragma unroll
            for (int nj = 0; nj < 4; nj++) {
                int col = bn + wn + nj * 8 + tc;
                float v0 = (acc[mi][nj][r * 2]     + bias[col])     * scale;
                float v1 = (acc[mi][nj][r * 2 + 1] + bias[col + 1]) * scale;
                if (do_gelu) {
                    v0 = 0.5f * v0 * (1.0f + erff(v0 * 0.7071067811865475f));
                    v1 = 0.5f * v1 * (1.0f + erff(v1 * 0.7071067811865475f));
                }
                if (res) {
                    float2 rv = *(const float2*)(res + row * (size_t)N + col);
                    v0 += rv.x; v1 += rv.y;
                }
                float2 o2; o2.x = v0; o2.y = v1;
                *(float2*)(C + row * (size_t)N + col) = o2;
            }
        }
    }
}

// ---------------- RoPE (in-place on q and k; only first 16 of 32 pairs rotate) ----------------
__global__ void rope_kernel(float* __restrict__ q, float* __restrict__ k) {
    int i = blockIdx.x * 256 + threadIdx.x;
    int j   = i & 15;
    int h   = (i >> 4) & 7;
    int row = (i >> 7) & (MROWS - 1);
    float* base = (i >> 22) ? k : q;
    int s = row & 511;
    float ang = (float)s * expf(-(float)j * 0.28782313662425575f);
    float sn, cs;
    sincosf(ang, &sn, &cs);
    float* p = base + (size_t)row * DMODEL + h * 64 + j;
    float x1 = p[0], x2 = p[32];
    p[0]  = x1 * cs - x2 * sn;
    p[32] = x2 * cs + x1 * sn;
}

// ---------------- Flash attention (fp32 SIMT) ----------------
__global__ __launch_bounds__(256) void attn_kernel(
    const float* __restrict__ q, const float* __restrict__ k,
    const float* __restrict__ v, float* __restrict__ o)
{
    extern __shared__ float smf[];
    float* Qs = smf;
    float* Ks = smf + 64 * APAD;
    float* Vs = smf + 2 * 64 * APAD;
    float* Ps = smf + 3 * 64 * APAD;

    int qt = blockIdx.x, bch = blockIdx.y;
    int bc = bch >> 3, h = bch & 7;
    int tid = threadIdx.x;
    int tx = tid & 15, ty = tid >> 4;

    const float* qb = q + (size_t)(bc * 512 + qt * 64) * 512 + h * 64;
    const float* kb = k + (size_t)(bc * 512) * 512 + h * 64;
    const float* vb = v + (size_t)(bc * 512) * 512 + h * 64;

    #pragma unroll
    for (int l = 0; l < 4; l++) {
        int f = tid + l * 256;
        int r = f >> 4, d4 = (f & 15) << 2;
        *(float4*)&Qs[r * APAD + d4] = *(const float4*)(qb + (size_t)r * 512 + d4);
    }

    float4 kreg[4], vreg[4];
    #pragma unroll
    for (int l = 0; l < 4; l++) {
        int f = tid + l * 256;
        int r = f >> 4, d4 = (f & 15) << 2;
        kreg[l] = *(const float4*)(kb + (size_t)r * 512 + d4);
        vreg[l] = *(const float4*)(vb + (size_t)r * 512 + d4);
    }

    float m_[4], l_[4], oacc[4][4];
    #pragma unroll
    for (int i = 0; i < 4; i++) {
        m_[i] = -1e30f; l_[i] = 0.f;
        #pragma unroll
        for (int c = 0; c < 4; c++) oacc[i][c] = 0.f;
    }

    for (int kt = 0; kt < 8; kt++) {
        __syncthreads();
        #pragma unroll
        for (int l = 0; l < 4; l++) {
            int f = tid + l * 256;
            int r = f >> 4, d4 = (f & 15) << 2;
            *(float4*)&Ks[r * APAD + d4] = kreg[l];
            *(float4*)&Vs[r * APAD + d4] = vreg[l];
        }
        __syncthreads();
        if (kt < 7) {
            #pragma unroll
            for (int l = 0; l < 4; l++) {
                int f = tid + l * 256;
                int r = f >> 4, d4 = (f & 15) << 2;
                kreg[l] = *(const float4*)(kb + (size_t)((kt + 1) * 64 + r) * 512 + d4);
                vreg[l] = *(const float4*)(vb + (size_t)((kt + 1) * 64 + r) * 512 + d4);
            }
        }

        float s[4][4];
        #pragma unroll
        for (int a = 0; a < 4; a++)
            #pragma unroll
            for (int b = 0; b < 4; b++) s[a][b] = 0.f;
        #pragma unroll
        for (int d4 = 0; d4 < 64; d4 += 4) {
            float4 qv[4], kv[4];
            #pragma unroll
            for (int ii = 0; ii < 4; ii++) qv[ii] = *(const float4*)&Qs[(ty + 16 * ii) * APAD + d4];
            #pragma unroll
            for (int jj = 0; jj < 4; jj++) kv[jj] = *(const float4*)&Ks[(tx + 16 * jj) * APAD + d4];
            #pragma unroll
            for (int ii = 0; ii < 4; ii++)
                #pragma unroll
                for (int jj = 0; jj < 4; jj++) {
                    s[ii][jj] = fmaf(qv[ii].x, kv[jj].x, s[ii][jj]);
                    s[ii][jj] = fmaf(qv[ii].y, kv[jj].y, s[ii][jj]);
                    s[ii][jj] = fmaf(qv[ii].z, kv[jj].z, s[ii][jj]);
                    s[ii][jj] = fmaf(qv[ii].w, kv[jj].w, s[ii][jj]);
                }
        }

        #pragma unroll
        for (int ii = 0; ii < 4; ii++) {
            float rm = fmaxf(fmaxf(s[ii][0], s[ii][1]), fmaxf(s[ii][2], s[ii][3]));
            #pragma unroll
            for (int off = 8; off > 0; off >>= 1)
                rm = fmaxf(rm, __shfl_xor_sync(0xffffffffu, rm, off));
            float mn = fmaxf(m_[ii], rm);
            float corr = __expf(m_[ii] - mn);
            float rs = 0.f;
            #pragma unroll
            for (int jj = 0; jj < 4; jj++) {
                s[ii][jj] = __expf(s[ii][jj] - mn);
                rs += s[ii][jj];
            }
            #pragma unroll
            for (int off = 8; off > 0; off >>= 1)
                rs += __shfl_xor_sync(0xffffffffu, rs, off);
            l_[ii] = l_[ii] * corr + rs;
            m_[ii] = mn;
            #pragma unroll
            for (int cc = 0; cc < 4; cc++) oacc[ii][cc] *= corr;
        }

        #pragma unroll
        for (int ii = 0; ii < 4; ii++)
            #pragma unroll
            for (int jj = 0; jj < 4; jj++)
                Ps[(ty + 16 * ii) * APAD + tx + 16 * jj] = s[ii][jj];
        __syncthreads();
        #pragma unroll 4
        for (int j = 0; j < 64; j++) {
            float pv[4], vv[4];
            #pragma unroll
            for (int ii = 0; ii < 4; ii++) pv[ii] = Ps[(ty + 16 * ii) * APAD + j];
            #pragma unroll
            for (int cc = 0; cc < 4; cc++) vv[cc] = Vs[j * APAD + tx + 16 * cc];
            #pragma unroll
            for (int ii = 0; ii < 4; ii++)
                #pragma unroll
                for (int cc = 0; cc < 4; cc++)
                    oacc[ii][cc] = fmaf(pv[ii], vv[cc], oacc[ii][cc]);
        }
    }

    float* ob = o + (size_t)(bc * 512 + qt * 64) * 512 + h * 64;
    #pragma unroll
    for (int ii = 0; ii < 4; ii++) {
        float inv = 1.0f / l_[ii];
        #pragma unroll
        for (int cc = 0; cc < 4; cc++)
            ob[(size_t)(ty + 16 * ii) * 512 + tx + 16 * cc] = oacc[ii][cc] * inv;
    }
}

// ---------------- launch ----------------
extern "C" void kernel_launch(void* const* d_in, const int* in_sizes, int n_in,
                              void* d_out, int out_size) {
    const float* x    = (const float*)d_in[0];
    const float* Wq   = (const float*)d_in[1];
    const float* bq   = (const float*)d_in[2];
    const float* Wk   = (const float*)d_in[3];
    const float* bk   = (const float*)d_in[4];
    const float* Wv   = (const float*)d_in[5];
    const float* bv   = (const float*)d_in[6];
    const float* Wo   = (const float*)d_in[7];
    const float* bo   = (const float*)d_in[8];
    const float* ln1g = (const float*)d_in[9];
    const float* ln1b = (const float*)d_in[10];
    const float* ln3g = (const float*)d_in[11];
    const float* ln3b = (const float*)d_in[12];
    const float* W1   = (const float*)d_in[13];
    const float* b1   = (const float*)d_in[14];
    const float* W2   = (const float*)d_in[15];
    const float* b2   = (const float*)d_in[16];
    float* out = (float*)d_out;

    float *hn, *qp, *kp, *vp, *op, *hp, *ffp, *wt;
    cudaGetSymbolAddress((void**)&hn,  g_hn);
    cudaGetSymbolAddress((void**)&qp,  g_q);
    cudaGetSymbolAddress((void**)&kp,  g_k);
    cudaGetSymbolAddress((void**)&vp,  g_v);
    cudaGetSymbolAddress((void**)&op,  g_o);
    cudaGetSymbolAddress((void**)&hp,  g_h);
    cudaGetSymbolAddress((void**)&ffp, g_ff);
    cudaGetSymbolAddress((void**)&wt,  g_wT);

    float* WqT = wt;
    float* WkT = wt + 262144;
    float* WvT = wt + 524288;
    float* WoT = wt + 786432;
    float* W1T = wt + 1048576;   // [2048][512]
    float* W2T = wt + 2097152;   // [512][2048]

    const int smemA = 4 * 64 * APAD * (int)sizeof(float);
    cudaFuncSetAttribute(attn_kernel, cudaFuncAttributeMaxDynamicSharedMemorySize, smemA);

    dim3 tb(32, 8);
    transpose_kernel<<<dim3(16, 16), tb>>>(Wq, WqT, 512, 512);
    transpose_kernel<<<dim3(16, 16), tb>>>(Wk, WkT, 512, 512);
    transpose_kernel<<<dim3(16, 16), tb>>>(Wv, WvT, 512, 512);
    transpose_kernel<<<dim3(16, 16), tb>>>(Wo, WoT, 512, 512);
    transpose_kernel<<<dim3(64, 16), tb>>>(W1, W1T, 512, 2048);
    transpose_kernel<<<dim3(16, 64), tb>>>(W2, W2T, 2048, 512);

    dim3 g512(DMODEL / 128, MROWS / 128);
    dim3 gffn(FFND / 128, MROWS / 128);

    ln_kernel<<<MROWS, 256>>>(x, ln1g, ln1b, hn);
    mma_gemm<<<g512, 256>>>(hn, WqT, bq, nullptr, qp, MROWS, DMODEL, DMODEL, 0.125f, 0);
    mma_gemm<<<g512, 256>>>(hn, WkT, bk, nullptr, kp, MROWS, DMODEL, DMODEL, 1.0f, 0);
    mma_gemm<<<g512, 256>>>(hn, WvT, bv, nullptr, vp, MROWS, DMODEL, DMODEL, 1.0f, 0);
    rope_kernel<<<32768, 256>>>(qp, kp);
    attn_kernel<<<dim3(8, 512), 256, smemA>>>(qp, kp, vp, op);
    mma_gemm<<<g512, 256>>>(op, WoT, bo, x, hp, MROWS, DMODEL, DMODEL, 1.0f, 0);
    ln_kernel<<<MROWS, 256>>>(hp, ln3g, ln3b, hn);
    mma_gemm<<<gffn, 256>>>(hn, W1T, b1, nullptr, ffp, MROWS, FFND, DMODEL, 1.0f, 1);
    mma_gemm<<<g512, 256>>>(ffp, W2T, b2, hp, out, MROWS, DMODEL, FFND, 1.0f, 0);
}

// round 4
// speedup vs baseline: 3.5545x; 1.4270x over previous
#include <cuda_runtime.h>
#include <cuda_fp16.h>
#include <math.h>
#include <stdint.h>

#define MROWS 32768
#define DMODEL 512
#define FFND 2048
#define SAPAD 40   // halfs per smem row in GEMM (32 data + 8 pad)

// ---------------- scratch ----------------
__device__ float g_hn[(size_t)MROWS * DMODEL];
__device__ float g_q [(size_t)MROWS * DMODEL];
__device__ float g_k [(size_t)MROWS * DMODEL];
__device__ float g_v [(size_t)MROWS * DMODEL];
__device__ float g_o [(size_t)MROWS * DMODEL];
__device__ float g_h [(size_t)MROWS * DMODEL];
__device__ float g_ff[(size_t)MROWS * FFND];
__device__ float g_wT[4 * 512 * 512 + 2 * 512 * 2048];   // transposed weights

__device__ __forceinline__ uint32_t smem_u32(const void* p) {
    uint32_t a;
    asm("{ .reg .u64 t; cvta.to.shared.u64 t, %1; cvt.u32.u64 %0, t; }" : "=r"(a) : "l"(p));
    return a;
}
__device__ __forceinline__ uint32_t pack_h2(float a, float b) {
    __half2 h = __floats2half2_rn(a, b);
    return *reinterpret_cast<uint32_t*>(&h);
}

#define LDMX4(r, addr) \
    asm volatile("ldmatrix.sync.aligned.m8n8.x4.shared.b16 {%0,%1,%2,%3}, [%4];" \
        : "=r"((r)[0]), "=r"((r)[1]), "=r"((r)[2]), "=r"((r)[3]) : "r"(addr))
#define LDMX4T(r, addr) \
    asm volatile("ldmatrix.sync.aligned.m8n8.x4.trans.shared.b16 {%0,%1,%2,%3}, [%4];" \
        : "=r"((r)[0]), "=r"((r)[1]), "=r"((r)[2]), "=r"((r)[3]) : "r"(addr))
#define MMA16816(c, a, b0, b1) \
    asm volatile("mma.sync.aligned.m16n8k16.row.col.f32.f16.f16.f32 " \
        "{%0,%1,%2,%3}, {%4,%5,%6,%7}, {%8,%9}, {%0,%1,%2,%3};" \
        : "+f"((c)[0]), "+f"((c)[1]), "+f"((c)[2]), "+f"((c)[3]) \
        : "r"((a)[0]), "r"((a)[1]), "r"((a)[2]), "r"((a)[3]), "r"(b0), "r"(b1))

// ---------------- weight transpose (R x C -> C x R) ----------------
__global__ void transpose_kernel(const float* __restrict__ in, float* __restrict__ out,
                                 int R, int C) {
    __shared__ float t[32][33];
    int bc = blockIdx.x * 32, br = blockIdx.y * 32;
    int x = threadIdx.x, y = threadIdx.y;
    #pragma unroll
    for (int i = 0; i < 32; i += 8)
        t[y + i][x] = in[(size_t)(br + y + i) * C + bc + x];
    __syncthreads();
    #pragma unroll
    for (int i = 0; i < 32; i += 8)
        out[(size_t)(bc + y + i) * R + br + x] = t[x][y + i];
}

// ---------------- LayerNorm ----------------
__global__ void ln_kernel(const float* __restrict__ x, const float* __restrict__ g,
                          const float* __restrict__ b, float* __restrict__ y) {
    int row = blockIdx.x;
    int tid = threadIdx.x;
    const float2* xr = (const float2*)(x + (size_t)row * DMODEL);
    float2 v = xr[tid];
    float s  = v.x + v.y;
    float ss = v.x * v.x + v.y * v.y;
    #pragma unroll
    for (int o = 16; o > 0; o >>= 1) {
        s  += __shfl_xor_sync(0xffffffffu, s,  o);
        ss += __shfl_xor_sync(0xffffffffu, ss, o);
    }
    __shared__ float sh[16];
    int w = tid >> 5, lane = tid & 31;
    if (lane == 0) { sh[w] = s; sh[8 + w] = ss; }
    __syncthreads();
    if (tid == 0) {
        float ts = 0.f, tss = 0.f;
        #pragma unroll
        for (int i = 0; i < 8; i++) { ts += sh[i]; tss += sh[8 + i]; }
        sh[0] = ts; sh[8] = tss;
    }
    __syncthreads();
    float mean = sh[0] * (1.0f / DMODEL);
    float var  = sh[8] * (1.0f / DMODEL) - mean * mean;
    float rstd = rsqrtf(var + 1e-5f);
    float2 gg = ((const float2*)g)[tid];
    float2 bb = ((const float2*)b)[tid];
    float2 o2;
    o2.x = (v.x - mean) * rstd * gg.x + bb.x;
    o2.y = (v.y - mean) * rstd * gg.y + bb.y;
    ((float2*)(y + (size_t)row * DMODEL))[tid] = o2;
}

// ---------------- HMMA fp16 GEMM: C = epi(A[MxK] @ Bt[NxK]^T) ----------------
__global__ __launch_bounds__(256) void mma_gemm(
    const float* __restrict__ A, const float* __restrict__ Bt,
    const float* __restrict__ bias, const float* __restrict__ res,
    float* __restrict__ C, int M, int N, int K, float scale, int do_gelu)
{
    __shared__ __half sm[20480];
    uint32_t smb = smem_u32(sm);

    int tid = threadIdx.x;
    int wid = tid >> 5, lane = tid & 31;
    int bm = blockIdx.y * 128, bn = blockIdx.x * 128;
    int wm = (wid >> 2) * 64, wn = (wid & 3) * 32;

    const float* Ab = A  + (size_t)bm * K;
    const float* Bb = Bt + (size_t)bn * K;

    int lrow = tid >> 1;
    int lko  = (tid & 1) * 16;

    uint32_t a_lrow = (uint32_t)(wm + (lane & 15));
    uint32_t a_lk   = (uint32_t)((lane >> 4) * 8);
    uint32_t b_lrow = (uint32_t)(wn + ((lane >> 4) << 3) + (lane & 7));
    uint32_t b_lk   = (uint32_t)(((lane >> 3) & 1) * 8);

    float acc[4][4][4];
    #pragma unroll
    for (int i = 0; i < 4; i++)
        #pragma unroll
        for (int j = 0; j < 4; j++)
            #pragma unroll
            for (int c = 0; c < 4; c++) acc[i][j][c] = 0.f;

    float4 ar[4], br[4];
    #pragma unroll
    for (int l = 0; l < 4; l++) {
        ar[l] = *(const float4*)(Ab + (size_t)lrow * K + lko + (l << 2));
        br[l] = *(const float4*)(Bb + (size_t)lrow * K + lko + (l << 2));
    }

    int nch = K >> 5;
    for (int ch = 0; ch < nch; ch++) {
        int sbase = (ch & 1) * 10240;
        __syncthreads();
        {
            union { __half2 h2[4]; uint4 u; } pa, pb;
            int off = sbase + lrow * SAPAD + lko;
            #pragma unroll
            for (int hh = 0; hh < 2; hh++) {
                pa.h2[0] = __floats2half2_rn(ar[hh*2].x, ar[hh*2].y);
                pa.h2[1] = __floats2half2_rn(ar[hh*2].z, ar[hh*2].w);
                pa.h2[2] = __floats2half2_rn(ar[hh*2+1].x, ar[hh*2+1].y);
                pa.h2[3] = __floats2half2_rn(ar[hh*2+1].z, ar[hh*2+1].w);
                *(uint4*)(&sm[off + hh * 8]) = pa.u;
                pb.h2[0] = __floats2half2_rn(br[hh*2].x, br[hh*2].y);
                pb.h2[1] = __floats2half2_rn(br[hh*2].z, br[hh*2].w);
                pb.h2[2] = __floats2half2_rn(br[hh*2+1].x, br[hh*2+1].y);
                pb.h2[3] = __floats2half2_rn(br[hh*2+1].z, br[hh*2+1].w);
                *(uint4*)(&sm[5120 + off + hh * 8]) = pb.u;
            }
        }
        __syncthreads();
        if (ch + 1 < nch) {
            int kc = (ch + 1) << 5;
            #pragma unroll
            for (int l = 0; l < 4; l++) {
                ar[l] = *(const float4*)(Ab + (size_t)lrow * K + kc + lko + (l << 2));
                br[l] = *(const float4*)(Bb + (size_t)lrow * K + kc + lko + (l << 2));
            }
        }
        uint32_t abase = smb + (uint32_t)sbase * 2;
        uint32_t bbase = abase + 10240u;
        #pragma unroll
        for (int ks = 0; ks < 2; ks++) {
            uint32_t kb = (uint32_t)(ks << 4);
            uint32_t afr[4][4], bfr[2][4];
            #pragma unroll
            for (int mi = 0; mi < 4; mi++) {
                uint32_t addr = abase + ((a_lrow + mi * 16) * SAPAD + kb + a_lk) * 2;
                LDMX4(afr[mi], addr);
            }
            #pragma unroll
            for (int nh = 0; nh < 2; nh++) {
                uint32_t addr = bbase + ((b_lrow + nh * 16) * SAPAD + kb + b_lk) * 2;
                LDMX4(bfr[nh], addr);
            }
            #pragma unroll
            for (int mi = 0; mi < 4; mi++)
                #pragma unroll
                for (int nj = 0; nj < 4; nj++) {
                    uint32_t b0 = bfr[nj >> 1][(nj & 1) * 2];
                    uint32_t b1 = bfr[nj >> 1][(nj & 1) * 2 + 1];
                    MMA16816(acc[mi][nj], afr[mi], b0, b1);
                }
        }
    }

    int g4 = lane >> 2, tc = (lane & 3) * 2;
    #pragma unroll
    for (int mi = 0; mi < 4; mi++) {
        #pragma unroll
        for (int r = 0; r < 2; r++) {
            size_t row = (size_t)(bm + wm + mi * 16 + g4 + r * 8);
            #pragma unroll
            for (int nj = 0; nj < 4; nj++) {
                int col = bn + wn + nj * 8 + tc;
                float v0 = (acc[mi][nj][r * 2]     + bias[col])     * scale;
                float v1 = (acc[mi][nj][r * 2 + 1] + bias[col + 1]) * scale;
                if (do_gelu) {
                    v0 = 0.5f * v0 * (1.0f + erff(v0 * 0.7071067811865475f));
                    v1 = 0.5f * v1 * (1.0f + erff(v1 * 0.7071067811865475f));
                }
                if (res) {
                    float2 rv = *(const float2*)(res + row * (size_t)N + col);
                    v0 += rv.x; v1 += rv.y;
                }
                float2 o2; o2.x = v0; o2.y = v1;
                *(float2*)(C + row * (size_t)N + col) = o2;
            }
        }
    }
}

// ---------------- RoPE ----------------
__global__ void rope_kernel(float* __restrict__ q, float* __restrict__ k) {
    int i = blockIdx.x * 256 + threadIdx.x;
    int j   = i & 15;
    int h   = (i >> 4) & 7;
    int row = (i >> 7) & (MROWS - 1);
    float* base = (i >> 22) ? k : q;
    int s = row & 511;
    float ang = (float)s * expf(-(float)j * 0.28782313662425575f);
    float sn, cs;
    sincosf(ang, &sn, &cs);
    float* p = base + (size_t)row * DMODEL + h * 64 + j;
    float x1 = p[0], x2 = p[32];
    p[0]  = x1 * cs - x2 * sn;
    p[32] = x2 * cs + x1 * sn;
}

// ---------------- HMMA flash attention ----------------
// Block: 128 thr (4 warps), 64 q-rows (16 per warp), 8 k-tiles of 64 keys.
// S accum (m16n8 C-frag) repacks directly into P A-frags for P@V.
#define ATP 72   // half pitch of 64-wide smem tiles
__global__ __launch_bounds__(128) void attn_mma_kernel(
    const float* __restrict__ q, const float* __restrict__ k,
    const float* __restrict__ v, float* __restrict__ o)
{
    __shared__ __half Qs[64 * ATP], Ks[64 * ATP], Vs[64 * ATP];
    uint32_t qsb = smem_u32(Qs), ksb = smem_u32(Ks), vsb = smem_u32(Vs);

    int qt = blockIdx.x, bch = blockIdx.y;
    int bc = bch >> 3, h = bch & 7;
    int tid = threadIdx.x;
    int w = tid >> 5, lane = tid & 31;
    int g = lane >> 2, t = lane & 3;

    const float* qb = q + (size_t)(bc * 512 + qt * 64) * 512 + h * 64;
    const float* kb = k + (size_t)(bc * 512) * 512 + h * 64;
    const float* vb = v + (size_t)(bc * 512) * 512 + h * 64;

    // load Q tile (64x64) -> half smem
    #pragma unroll
    for (int l = 0; l < 8; l++) {
        int f = tid + l * 128;
        int r = f >> 4, c4 = (f & 15) << 2;
        float4 qv = *(const float4*)(qb + (size_t)r * 512 + c4);
        *(__half2*)(&Qs[r * ATP + c4])     = __floats2half2_rn(qv.x, qv.y);
        *(__half2*)(&Qs[r * ATP + c4 + 2]) = __floats2half2_rn(qv.z, qv.w);
    }
    __syncthreads();

    // Q A-frags (persistent in regs): rows 16w..16w+15, 4 k16 steps
    uint32_t qf[4][4];
    {
        uint32_t arow = (uint32_t)(16 * w + (lane & 15));
        uint32_t akof = (uint32_t)((lane >> 4) << 3);
        #pragma unroll
        for (int ks = 0; ks < 4; ks++) {
            uint32_t addr = qsb + ((arow * ATP + (ks << 4) + akof) << 1);
            LDMX4(qf[ks], addr);
        }
    }

    float m0 = -1e30f, m1 = -1e30f, l0 = 0.f, l1 = 0.f;
    float of[8][4];
    #pragma unroll
    for (int nj = 0; nj < 8; nj++)
        #pragma unroll
        for (int c = 0; c < 4; c++) of[nj][c] = 0.f;

    // ldmatrix lane-address components
    uint32_t kb_row = (uint32_t)(((lane >> 4) << 3) + (lane & 7));   // non-trans B (K)
    uint32_t kb_kof = (uint32_t)(((lane >> 3) & 1) << 3);
    uint32_t vb_row = (uint32_t)((((lane >> 3) & 1) << 3) + (lane & 7)); // trans B (V)
    uint32_t vb_cof = (uint32_t)((lane >> 4) << 3);

    for (int kt = 0; kt < 8; kt++) {
        __syncthreads();
        #pragma unroll
        for (int l = 0; l < 8; l++) {
            int f = tid + l * 128;
            int r = f >> 4, c4 = (f & 15) << 2;
            float4 kv = *(const float4*)(kb + (size_t)(kt * 64 + r) * 512 + c4);
            float4 vv = *(const float4*)(vb + (size_t)(kt * 64 + r) * 512 + c4);
            *(__half2*)(&Ks[r * ATP + c4])     = __floats2half2_rn(kv.x, kv.y);
            *(__half2*)(&Ks[r * ATP + c4 + 2]) = __floats2half2_rn(kv.z, kv.w);
            *(__half2*)(&Vs[r * ATP + c4])     = __floats2half2_rn(vv.x, vv.y);
            *(__half2*)(&Vs[r * ATP + c4 + 2]) = __floats2half2_rn(vv.z, vv.w);
        }
        __syncthreads();

        // S = Q @ K^T  (16 x 64 per warp)
        float sf[8][4];
        #pragma unroll
        for (int nj = 0; nj < 8; nj++)
            #pragma unroll
            for (int c = 0; c < 4; c++) sf[nj][c] = 0.f;
        #pragma unroll
        for (int ks = 0; ks < 4; ks++) {
            #pragma unroll
            for (int nh = 0; nh < 4; nh++) {
                uint32_t addr = ksb + ((((nh << 4) + kb_row) * ATP + (ks << 4) + kb_kof) << 1);
                uint32_t kf[4];
                LDMX4(kf, addr);
                MMA16816(sf[2 * nh],     qf[ks], kf[0], kf[1]);
                MMA16816(sf[2 * nh + 1], qf[ks], kf[2], kf[3]);
            }
        }

        // online softmax (rows g and g+8)
        float rm0 = -1e30f, rm1 = -1e30f;
        #pragma unroll
        for (int nj = 0; nj < 8; nj++) {
            rm0 = fmaxf(rm0, fmaxf(sf[nj][0], sf[nj][1]));
            rm1 = fmaxf(rm1, fmaxf(sf[nj][2], sf[nj][3]));
        }
        #pragma unroll
        for (int off = 1; off <= 2; off <<= 1) {
            rm0 = fmaxf(rm0, __shfl_xor_sync(0xffffffffu, rm0, off));
            rm1 = fmaxf(rm1, __shfl_xor_sync(0xffffffffu, rm1, off));
        }
        float mn0 = fmaxf(m0, rm0), mn1 = fmaxf(m1, rm1);
        float cr0 = __expf(m0 - mn0), cr1 = __expf(m1 - mn1);
        float rs0 = 0.f, rs1 = 0.f;
        #pragma unroll
        for (int nj = 0; nj < 8; nj++) {
            sf[nj][0] = __expf(sf[nj][0] - mn0);
            sf[nj][1] = __expf(sf[nj][1] - mn0);
            sf[nj][2] = __expf(sf[nj][2] - mn1);
            sf[nj][3] = __expf(sf[nj][3] - mn1);
            rs0 += sf[nj][0] + sf[nj][1];
            rs1 += sf[nj][2] + sf[nj][3];
        }
        #pragma unroll
        for (int off = 1; off <= 2; off <<= 1) {
            rs0 += __shfl_xor_sync(0xffffffffu, rs0, off);
            rs1 += __shfl_xor_sync(0xffffffffu, rs1, off);
        }
        l0 = l0 * cr0 + rs0;
        l1 = l1 * cr1 + rs1;
        m0 = mn0; m1 = mn1;
        #pragma unroll
        for (int nj = 0; nj < 8; nj++) {
            of[nj][0] *= cr0; of[nj][1] *= cr0;
            of[nj][2] *= cr1; of[nj][3] *= cr1;
        }

        // repack S (C-frags) -> P (A-frags), 4 k16 steps over keys
        uint32_t pf[4][4];
        #pragma unroll
        for (int ks = 0; ks < 4; ks++) {
            pf[ks][0] = pack_h2(sf[2 * ks][0],     sf[2 * ks][1]);
            pf[ks][1] = pack_h2(sf[2 * ks][2],     sf[2 * ks][3]);
            pf[ks][2] = pack_h2(sf[2 * ks + 1][0], sf[2 * ks + 1][1]);
            pf[ks][3] = pack_h2(sf[2 * ks + 1][2], sf[2 * ks + 1][3]);
        }

        // O += P @ V  (contract over 64 keys; V via ldmatrix.trans)
        #pragma unroll
        for (int ks = 0; ks < 4; ks++) {
            #pragma unroll
            for (int nh = 0; nh < 4; nh++) {
                uint32_t addr = vsb + ((((ks << 4) + vb_row) * ATP + (nh << 4) + vb_cof) << 1);
                uint32_t vf[4];
                LDMX4T(vf, addr);
                MMA16816(of[2 * nh],     pf[ks], vf[0], vf[1]);
                MMA16816(of[2 * nh + 1], pf[ks], vf[2], vf[3]);
            }
        }
    }

    float* ob = o + (size_t)(bc * 512 + qt * 64) * 512 + h * 64;
    float inv0 = 1.0f / l0, inv1 = 1.0f / l1;
    #pragma unroll
    for (int nj = 0; nj < 8; nj++) {
        int col = nj * 8 + t * 2;
        float2 o0; o0.x = of[nj][0] * inv0; o0.y = of[nj][1] * inv0;
        float2 o1; o1.x = of[nj][2] * inv1; o1.y = of[nj][3] * inv1;
        *(float2*)(ob + (size_t)(16 * w + g) * 512 + col)     = o0;
        *(float2*)(ob + (size_t)(16 * w + g + 8) * 512 + col) = o1;
    }
}

// ---------------- launch ----------------
extern "C" void kernel_launch(void* const* d_in, const int* in_sizes, int n_in,
                              void* d_out, int out_size) {
    const float* x    = (const float*)d_in[0];
    const float* Wq   = (const float*)d_in[1];
    const float* bq   = (const float*)d_in[2];
    const float* Wk   = (const float*)d_in[3];
    const float* bk   = (const float*)d_in[4];
    const float* Wv   = (const float*)d_in[5];
    const float* bv   = (const float*)d_in[6];
    const float* Wo   = (const float*)d_in[7];
    const float* bo   = (const float*)d_in[8];
    const float* ln1g = (const float*)d_in[9];
    const float* ln1b = (const float*)d_in[10];
    const float* ln3g = (const float*)d_in[11];
    const float* ln3b = (const float*)d_in[12];
    const float* W1   = (const float*)d_in[13];
    const float* b1   = (const float*)d_in[14];
    const float* W2   = (const float*)d_in[15];
    const float* b2   = (const float*)d_in[16];
    float* out = (float*)d_out;

    float *hn, *qp, *kp, *vp, *op, *hp, *ffp, *wt;
    cudaGetSymbolAddress((void**)&hn,  g_hn);
    cudaGetSymbolAddress((void**)&qp,  g_q);
    cudaGetSymbolAddress((void**)&kp,  g_k);
    cudaGetSymbolAddress((void**)&vp,  g_v);
    cudaGetSymbolAddress((void**)&op,  g_o);
    cudaGetSymbolAddress((void**)&hp,  g_h);
    cudaGetSymbolAddress((void**)&ffp, g_ff);
    cudaGetSymbolAddress((void**)&wt,  g_wT);

    float* WqT = wt;
    float* WkT = wt + 262144;
    float* WvT = wt + 524288;
    float* WoT = wt + 786432;
    float* W1T = wt + 1048576;
    float* W2T = wt + 2097152;

    dim3 tb(32, 8);
    transpose_kernel<<<dim3(16, 16), tb>>>(Wq, WqT, 512, 512);
    transpose_kernel<<<dim3(16, 16), tb>>>(Wk, WkT, 512, 512);
    transpose_kernel<<<dim3(16, 16), tb>>>(Wv, WvT, 512, 512);
    transpose_kernel<<<dim3(16, 16), tb>>>(Wo, WoT, 512, 512);
    transpose_kernel<<<dim3(64, 16), tb>>>(W1, W1T, 512, 2048);
    transpose_kernel<<<dim3(16, 64), tb>>>(W2, W2T, 2048, 512);

    dim3 g512(DMODEL / 128, MROWS / 128);
    dim3 gffn(FFND / 128, MROWS / 128);

    ln_kernel<<<MROWS, 256>>>(x, ln1g, ln1b, hn);
    mma_gemm<<<g512, 256>>>(hn, WqT, bq, nullptr, qp, MROWS, DMODEL, DMODEL, 0.125f, 0);
    mma_gemm<<<g512, 256>>>(hn, WkT, bk, nullptr, kp, MROWS, DMODEL, DMODEL, 1.0f, 0);
    mma_gemm<<<g512, 256>>>(hn, WvT, bv, nullptr, vp, MROWS, DMODEL, DMODEL, 1.0f, 0);
    rope_kernel<<<32768, 256>>>(qp, kp);
    attn_mma_kernel<<<dim3(8, 512), 128>>>(qp, kp, vp, op);
    mma_gemm<<<g512, 256>>>(op, WoT, bo, x, hp, MROWS, DMODEL, DMODEL, 1.0f, 0);
    ln_kernel<<<MROWS, 256>>>(hp, ln3g, ln3b, hn);
    mma_gemm<<<gffn, 256>>>(hn, W1T, b1, nullptr, ffp, MROWS, FFND, DMODEL, 1.0f, 1);
    mma_gemm<<<g512, 256>>>(ffp, W2T, b2, hp, out, MROWS, DMODEL, FFND, 1.0f, 0);
}

// round 5
// speedup vs baseline: 5.3893x; 1.5162x over previous
#include <cuda_runtime.h>
#include <cuda_fp16.h>
#include <math.h>
#include <stdint.h>

#define MROWS 32768
#define DMODEL 512
#define FFND 2048
#define SAPAD 40   // halfs per smem row in GEMM (32 data + 8 pad)
#define ATP 72     // half pitch of 64-wide attention smem tiles

// ---------------- scratch ----------------
__device__ __half g_hn [(size_t)MROWS * DMODEL];
__device__ __half g_qkv[(size_t)MROWS * 1536];
__device__ __half g_oh [(size_t)MROWS * DMODEL];
__device__ float  g_h  [(size_t)MROWS * DMODEL];
__device__ __half g_ffh[(size_t)MROWS * FFND];
__device__ __half g_wTh[512 * 1536 + 512 * 512 + 512 * 2048 + 2048 * 512];
__device__ float  g_bqkv[1536];

__device__ __forceinline__ uint32_t smem_u32(const void* p) {
    uint32_t a;
    asm("{ .reg .u64 t; cvta.to.shared.u64 t, %1; cvt.u32.u64 %0, t; }" : "=r"(a) : "l"(p));
    return a;
}
__device__ __forceinline__ uint32_t pack_h2(float a, float b) {
    __half2 h = __floats2half2_rn(a, b);
    return *reinterpret_cast<uint32_t*>(&h);
}

#define LDMX4(r, addr) \
    asm volatile("ldmatrix.sync.aligned.m8n8.x4.shared.b16 {%0,%1,%2,%3}, [%4];" \
        : "=r"((r)[0]), "=r"((r)[1]), "=r"((r)[2]), "=r"((r)[3]) : "r"(addr))
#define LDMX4T(r, addr) \
    asm volatile("ldmatrix.sync.aligned.m8n8.x4.trans.shared.b16 {%0,%1,%2,%3}, [%4];" \
        : "=r"((r)[0]), "=r"((r)[1]), "=r"((r)[2]), "=r"((r)[3]) : "r"(addr))
#define MMA16816(c, a, b0, b1) \
    asm volatile("mma.sync.aligned.m16n8k16.row.col.f32.f16.f16.f32 " \
        "{%0,%1,%2,%3}, {%4,%5,%6,%7}, {%8,%9}, {%0,%1,%2,%3};" \
        : "+f"((c)[0]), "+f"((c)[1]), "+f"((c)[2]), "+f"((c)[3]) \
        : "r"((a)[0]), "r"((a)[1]), "r"((a)[2]), "r"((a)[3]), "r"(b0), "r"(b1))
#define CPASYNC16(dst, src) \
    asm volatile("cp.async.ca.shared.global [%0], [%1], 16;" :: "r"(dst), "l"(src))
#define CPCOMMIT() asm volatile("cp.async.commit_group;" ::: "memory")
#define CPWAIT(n)  asm volatile("cp.async.wait_group %0;" :: "n"(n) : "memory")

// ---------------- weight transpose + fp16 convert (R x C -> C x R) ----------------
__global__ void transpose_h(const float* __restrict__ in, __half* __restrict__ out,
                            int R, int C) {
    __shared__ float t[32][33];
    int bc = blockIdx.x * 32, br = blockIdx.y * 32;
    int x = threadIdx.x, y = threadIdx.y;
    #pragma unroll
    for (int i = 0; i < 32; i += 8)
        t[y + i][x] = in[(size_t)(br + y + i) * C + bc + x];
    __syncthreads();
    #pragma unroll
    for (int i = 0; i < 32; i += 8)
        out[(size_t)(bc + y + i) * R + br + x] = __float2half_rn(t[x][y + i]);
}

__global__ void concat_bias(const float* __restrict__ bq, const float* __restrict__ bk,
                            const float* __restrict__ bv, float* __restrict__ o) {
    int i = blockIdx.x * 256 + threadIdx.x;
    o[i] = i < 512 ? bq[i] : (i < 1024 ? bk[i - 512] : bv[i - 1024]);
}

// ---------------- LayerNorm: fp32 in, fp16 out ----------------
__global__ void ln_kernel(const float* __restrict__ x, const float* __restrict__ g,
                          const float* __restrict__ b, __half* __restrict__ y) {
    int row = blockIdx.x;
    int tid = threadIdx.x;
    const float2* xr = (const float2*)(x + (size_t)row * DMODEL);
    float2 v = xr[tid];
    float s  = v.x + v.y;
    float ss = v.x * v.x + v.y * v.y;
    #pragma unroll
    for (int o = 16; o > 0; o >>= 1) {
        s  += __shfl_xor_sync(0xffffffffu, s,  o);
        ss += __shfl_xor_sync(0xffffffffu, ss, o);
    }
    __shared__ float sh[16];
    int w = tid >> 5, lane = tid & 31;
    if (lane == 0) { sh[w] = s; sh[8 + w] = ss; }
    __syncthreads();
    if (tid == 0) {
        float ts = 0.f, tss = 0.f;
        #pragma unroll
        for (int i = 0; i < 8; i++) { ts += sh[i]; tss += sh[8 + i]; }
        sh[0] = ts; sh[8] = tss;
    }
    __syncthreads();
    float mean = sh[0] * (1.0f / DMODEL);
    float var  = sh[8] * (1.0f / DMODEL) - mean * mean;
    float rstd = rsqrtf(var + 1e-5f);
    float2 gg = ((const float2*)g)[tid];
    float2 bb = ((const float2*)b)[tid];
    ((__half2*)(y + (size_t)row * DMODEL))[tid] =
        __floats2half2_rn((v.x - mean) * rstd * gg.x + bb.x,
                          (v.y - mean) * rstd * gg.y + bb.y);
}

// ---------------- HMMA fp16 GEMM: out = epi(A[MxK] @ Bt[NxK]^T + bias) ----------------
// half A/B via cp.async double buffer; output half (Ch) or float (Cf, +res).
__global__ __launch_bounds__(256) void hgemm(
    const __half* __restrict__ A, const __half* __restrict__ Bt,
    const float* __restrict__ bias, const float* __restrict__ res,
    __half* __restrict__ Ch, float* __restrict__ Cf,
    int M, int N, int K, int do_gelu)
{
    __shared__ __half sm[20480];   // 2 stages x (A 5120 + B 5120) halves
    uint32_t smb = smem_u32(sm);

    int tid = threadIdx.x;
    int wid = tid >> 5, lane = tid & 31;
    int bm = blockIdx.y * 128, bn = blockIdx.x * 128;
    int wm = (wid >> 2) * 64, wn = (wid & 3) * 32;

    const __half* Ab = A  + (size_t)bm * K;
    const __half* Bb = Bt + (size_t)bn * K;

    int lrow = tid >> 1;
    int lko  = (tid & 1) * 16;
    uint32_t sA = smb + (uint32_t)(lrow * SAPAD + lko) * 2;

    uint32_t a_lrow = (uint32_t)(wm + (lane & 15));
    uint32_t a_lk   = (uint32_t)((lane >> 4) * 8);
    uint32_t b_lrow = (uint32_t)(wn + ((lane >> 4) << 3) + (lane & 7));
    uint32_t b_lk   = (uint32_t)(((lane >> 3) & 1) * 8);

    float acc[4][4][4];
    #pragma unroll
    for (int i = 0; i < 4; i++)
        #pragma unroll
        for (int j = 0; j < 4; j++)
            #pragma unroll
            for (int c = 0; c < 4; c++) acc[i][j][c] = 0.f;

    int nch = K >> 5;
    // prologue: stage 0
    {
        const __half* ga = Ab + (size_t)lrow * K + lko;
        const __half* gb = Bb + (size_t)lrow * K + lko;
        CPASYNC16(sA,             ga);
        CPASYNC16(sA + 16,        ga + 8);
        CPASYNC16(sA + 10240,     gb);
        CPASYNC16(sA + 10240 + 16, gb + 8);
        CPCOMMIT();
    }

    for (int ch = 0; ch < nch; ch++) {
        int s = ch & 1;
        if (ch + 1 < nch) {
            int kc = (ch + 1) << 5;
            uint32_t d = sA + (uint32_t)((s ^ 1) * 20480);
            const __half* ga = Ab + (size_t)lrow * K + kc + lko;
            const __half* gb = Bb + (size_t)lrow * K + kc + lko;
            CPASYNC16(d,              ga);
            CPASYNC16(d + 16,         ga + 8);
            CPASYNC16(d + 10240,      gb);
            CPASYNC16(d + 10240 + 16, gb + 8);
            CPCOMMIT();
            CPWAIT(1);
        } else {
            CPWAIT(0);
        }
        __syncthreads();

        uint32_t abase = smb + (uint32_t)(s * 20480);
        uint32_t bbase = abase + 10240u;
        #pragma unroll
        for (int ks = 0; ks < 2; ks++) {
            uint32_t kb = (uint32_t)(ks << 4);
            uint32_t afr[4][4], bfr[2][4];
            #pragma unroll
            for (int mi = 0; mi < 4; mi++) {
                uint32_t addr = abase + ((a_lrow + mi * 16) * SAPAD + kb + a_lk) * 2;
                LDMX4(afr[mi], addr);
            }
            #pragma unroll
            for (int nh = 0; nh < 2; nh++) {
                uint32_t addr = bbase + ((b_lrow + nh * 16) * SAPAD + kb + b_lk) * 2;
                LDMX4(bfr[nh], addr);
            }
            #pragma unroll
            for (int mi = 0; mi < 4; mi++)
                #pragma unroll
                for (int nj = 0; nj < 4; nj++) {
                    uint32_t b0 = bfr[nj >> 1][(nj & 1) * 2];
                    uint32_t b1 = bfr[nj >> 1][(nj & 1) * 2 + 1];
                    MMA16816(acc[mi][nj], afr[mi], b0, b1);
                }
        }
        __syncthreads();
    }

    int g4 = lane >> 2, tc = (lane & 3) * 2;
    #pragma unroll
    for (int mi = 0; mi < 4; mi++) {
        #pragma unroll
        for (int r = 0; r < 2; r++) {
            size_t row = (size_t)(bm + wm + mi * 16 + g4 + r * 8);
            #pragma unroll
            for (int nj = 0; nj < 4; nj++) {
                int col = bn + wn + nj * 8 + tc;
                float v0 = acc[mi][nj][r * 2]     + bias[col];
                float v1 = acc[mi][nj][r * 2 + 1] + bias[col + 1];
                if (do_gelu) {
                    v0 = 0.5f * v0 * (1.0f + erff(v0 * 0.7071067811865475f));
                    v1 = 0.5f * v1 * (1.0f + erff(v1 * 0.7071067811865475f));
                }
                if (Ch) {
                    *(__half2*)(Ch + row * (size_t)N + col) = __floats2half2_rn(v0, v1);
                } else {
                    if (res) {
                        float2 rv = *(const float2*)(res + row * (size_t)N + col);
                        v0 += rv.x; v1 += rv.y;
                    }
                    float2 o2; o2.x = v0; o2.y = v1;
                    *(float2*)(Cf + row * (size_t)N + col) = o2;
                }
            }
        }
    }
}

// ---------------- RoPE (in-place on packed qkv, half) ----------------
__global__ void rope_kernel(__half* __restrict__ qkv) {
    int i = blockIdx.x * 256 + threadIdx.x;
    int j   = i & 15;
    int h   = (i >> 4) & 7;
    int row = (i >> 7) & (MROWS - 1);
    int isk = (i >> 22) & 1;
    int s = row & 511;
    float ang = (float)s * expf(-(float)j * 0.28782313662425575f);
    float sn, cs;
    sincosf(ang, &sn, &cs);
    __half* p = qkv + (size_t)row * 1536 + isk * 512 + h * 64 + j;
    float x1 = __half2float(p[0]), x2 = __half2float(p[32]);
    p[0]  = __float2half_rn(x1 * cs - x2 * sn);
    p[32] = __float2half_rn(x2 * cs + x1 * sn);
}

// ---------------- HMMA flash attention (half qkv in, half o out) ----------------
__global__ __launch_bounds__(128) void attn_mma_kernel(
    const __half* __restrict__ qkv, __half* __restrict__ o)
{
    __shared__ __half Qs[64 * ATP], Ks[64 * ATP], Vs[64 * ATP];
    uint32_t qsb = smem_u32(Qs), ksb = smem_u32(Ks), vsb = smem_u32(Vs);

    int qt = blockIdx.x, bch = blockIdx.y;
    int bc = bch >> 3, h = bch & 7;
    int tid = threadIdx.x;
    int w = tid >> 5, lane = tid & 31;
    int g = lane >> 2, t = lane & 3;

    const __half* qb = qkv + (size_t)(bc * 512 + qt * 64) * 1536 + h * 64;
    const __half* kb = qkv + (size_t)(bc * 512) * 1536 + 512 + h * 64;
    const __half* vb = qkv + (size_t)(bc * 512) * 1536 + 1024 + h * 64;

    #pragma unroll
    for (int l = 0; l < 4; l++) {
        int f = tid + l * 128;
        int r = f >> 3, c8 = (f & 7) << 3;
        *(uint4*)&Qs[r * ATP + c8] = *(const uint4*)(qb + (size_t)r * 1536 + c8);
    }
    __syncthreads();

    uint32_t qf[4][4];
    {
        uint32_t arow = (uint32_t)(16 * w + (lane & 15));
        uint32_t akof = (uint32_t)((lane >> 4) << 3);
        #pragma unroll
        for (int ks = 0; ks < 4; ks++) {
            uint32_t addr = qsb + ((arow * ATP + (ks << 4) + akof) << 1);
            LDMX4(qf[ks], addr);
        }
    }

    float m0 = -1e30f, m1 = -1e30f, l0 = 0.f, l1 = 0.f;
    float of[8][4];
    #pragma unroll
    for (int nj = 0; nj < 8; nj++)
        #pragma unroll
        for (int c = 0; c < 4; c++) of[nj][c] = 0.f;

    uint32_t kb_row = (uint32_t)(((lane >> 4) << 3) + (lane & 7));
    uint32_t kb_kof = (uint32_t)(((lane >> 3) & 1) << 3);
    uint32_t vb_row = (uint32_t)((((lane >> 3) & 1) << 3) + (lane & 7));
    uint32_t vb_cof = (uint32_t)((lane >> 4) << 3);

    for (int kt = 0; kt < 8; kt++) {
        __syncthreads();
        #pragma unroll
        for (int l = 0; l < 4; l++) {
            int f = tid + l * 128;
            int r = f >> 3, c8 = (f & 7) << 3;
            *(uint4*)&Ks[r * ATP + c8] = *(const uint4*)(kb + (size_t)(kt * 64 + r) * 1536 + c8);
            *(uint4*)&Vs[r * ATP + c8] = *(const uint4*)(vb + (size_t)(kt * 64 + r) * 1536 + c8);
        }
        __syncthreads();

        // S = (Q @ K^T) * 0.125
        float sf[8][4];
        #pragma unroll
        for (int nj = 0; nj < 8; nj++)
            #pragma unroll
            for (int c = 0; c < 4; c++) sf[nj][c] = 0.f;
        #pragma unroll
        for (int ks = 0; ks < 4; ks++) {
            #pragma unroll
            for (int nh = 0; nh < 4; nh++) {
                uint32_t addr = ksb + ((((nh << 4) + kb_row) * ATP + (ks << 4) + kb_kof) << 1);
                uint32_t kf[4];
                LDMX4(kf, addr);
                MMA16816(sf[2 * nh],     qf[ks], kf[0], kf[1]);
                MMA16816(sf[2 * nh + 1], qf[ks], kf[2], kf[3]);
            }
        }
        #pragma unroll
        for (int nj = 0; nj < 8; nj++)
            #pragma unroll
            for (int c = 0; c < 4; c++) sf[nj][c] *= 0.125f;

        // online softmax (rows g and g+8)
        float rm0 = -1e30f, rm1 = -1e30f;
        #pragma unroll
        for (int nj = 0; nj < 8; nj++) {
            rm0 = fmaxf(rm0, fmaxf(sf[nj][0], sf[nj][1]));
            rm1 = fmaxf(rm1, fmaxf(sf[nj][2], sf[nj][3]));
        }
        #pragma unroll
        for (int off = 1; off <= 2; off <<= 1) {
            rm0 = fmaxf(rm0, __shfl_xor_sync(0xffffffffu, rm0, off));
            rm1 = fmaxf(rm1, __shfl_xor_sync(0xffffffffu, rm1, off));
        }
        float mn0 = fmaxf(m0, rm0), mn1 = fmaxf(m1, rm1);
        float cr0 = __expf(m0 - mn0), cr1 = __expf(m1 - mn1);
        float rs0 = 0.f, rs1 = 0.f;
        #pragma unroll
        for (int nj = 0; nj < 8; nj++) {
            sf[nj][0] = __expf(sf[nj][0] - mn0);
            sf[nj][1] = __expf(sf[nj][1] - mn0);
            sf[nj][2] = __expf(sf[nj][2] - mn1);
            sf[nj][3] = __expf(sf[nj][3] - mn1);
            rs0 += sf[nj][0] + sf[nj][1];
            rs1 += sf[nj][2] + sf[nj][3];
        }
        #pragma unroll
        for (int off = 1; off <= 2; off <<= 1) {
            rs0 += __shfl_xor_sync(0xffffffffu, rs0, off);
            rs1 += __shfl_xor_sync(0xffffffffu, rs1, off);
        }
        l0 = l0 * cr0 + rs0;
        l1 = l1 * cr1 + rs1;
        m0 = mn0; m1 = mn1;
        #pragma unroll
        for (int nj = 0; nj < 8; nj++) {
            of[nj][0] *= cr0; of[nj][1] *= cr0;
            of[nj][2] *= cr1; of[nj][3] *= cr1;
        }

        uint32_t pf[4][4];
        #pragma unroll
        for (int ks = 0; ks < 4; ks++) {
            pf[ks][0] = pack_h2(sf[2 * ks][0],     sf[2 * ks][1]);
            pf[ks][1] = pack_h2(sf[2 * ks][2],     sf[2 * ks][3]);
            pf[ks][2] = pack_h2(sf[2 * ks + 1][0], sf[2 * ks + 1][1]);
            pf[ks][3] = pack_h2(sf[2 * ks + 1][2], sf[2 * ks + 1][3]);
        }

        #pragma unroll
        for (int ks = 0; ks < 4; ks++) {
            #pragma unroll
            for (int nh = 0; nh < 4; nh++) {
                uint32_t addr = vsb + ((((ks << 4) + vb_row) * ATP + (nh << 4) + vb_cof) << 1);
                uint32_t vf[4];
                LDMX4T(vf, addr);
                MMA16816(of[2 * nh],     pf[ks], vf[0], vf[1]);
                MMA16816(of[2 * nh + 1], pf[ks], vf[2], vf[3]);
            }
        }
    }

    __half* ob = o + (size_t)(bc * 512 + qt * 64) * 512 + h * 64;
    float inv0 = 1.0f / l0, inv1 = 1.0f / l1;
    #pragma unroll
    for (int nj = 0; nj < 8; nj++) {
        int col = nj * 8 + t * 2;
        *(__half2*)(ob + (size_t)(16 * w + g) * 512 + col) =
            __floats2half2_rn(of[nj][0] * inv0, of[nj][1] * inv0);
        *(__half2*)(ob + (size_t)(16 * w + g + 8) * 512 + col) =
            __floats2half2_rn(of[nj][2] * inv1, of[nj][3] * inv1);
    }
}

// ---------------- launch ----------------
extern "C" void kernel_launch(void* const* d_in, const int* in_sizes, int n_in,
                              void* d_out, int out_size) {
    const float* x    = (const float*)d_in[0];
    const float* Wq   = (const float*)d_in[1];
    const float* bq   = (const float*)d_in[2];
    const float* Wk   = (const float*)d_in[3];
    const float* bk   = (const float*)d_in[4];
    const float* Wv   = (const float*)d_in[5];
    const float* bv   = (const float*)d_in[6];
    const float* Wo   = (const float*)d_in[7];
    const float* bo   = (const float*)d_in[8];
    const float* ln1g = (const float*)d_in[9];
    const float* ln1b = (const float*)d_in[10];
    const float* ln3g = (const float*)d_in[11];
    const float* ln3b = (const float*)d_in[12];
    const float* W1   = (const float*)d_in[13];
    const float* b1   = (const float*)d_in[14];
    const float* W2   = (const float*)d_in[15];
    const float* b2   = (const float*)d_in[16];
    float* out = (float*)d_out;

    __half *hn, *qkv, *oh, *ffh, *wth;
    float *hp, *bqkv;
    cudaGetSymbolAddress((void**)&hn,   g_hn);
    cudaGetSymbolAddress((void**)&qkv,  g_qkv);
    cudaGetSymbolAddress((void**)&oh,   g_oh);
    cudaGetSymbolAddress((void**)&hp,   g_h);
    cudaGetSymbolAddress((void**)&ffh,  g_ffh);
    cudaGetSymbolAddress((void**)&wth,  g_wTh);
    cudaGetSymbolAddress((void**)&bqkv, g_bqkv);

    __half* WqkvT = wth;                       // [1536][512]
    __half* WoT   = wth + 512 * 1536;          // [512][512]
    __half* W1T   = WoT + 512 * 512;           // [2048][512]
    __half* W2T   = W1T + 512 * 2048;          // [512][2048]

    dim3 tb(32, 8);
    transpose_h<<<dim3(16, 16), tb>>>(Wq, WqkvT,             512, 512);
    transpose_h<<<dim3(16, 16), tb>>>(Wk, WqkvT + 512 * 512, 512, 512);
    transpose_h<<<dim3(16, 16), tb>>>(Wv, WqkvT + 1024 * 512, 512, 512);
    transpose_h<<<dim3(16, 16), tb>>>(Wo, WoT, 512, 512);
    transpose_h<<<dim3(64, 16), tb>>>(W1, W1T, 512, 2048);
    transpose_h<<<dim3(16, 64), tb>>>(W2, W2T, 2048, 512);
    concat_bias<<<6, 256>>>(bq, bk, bv, bqkv);

    dim3 g512(4, MROWS / 128);
    dim3 gqkv(12, MROWS / 128);
    dim3 gffn(16, MROWS / 128);

    ln_kernel<<<MROWS, 256>>>(x, ln1g, ln1b, hn);
    hgemm<<<gqkv, 256>>>(hn, WqkvT, bqkv, nullptr, qkv, nullptr, MROWS, 1536, DMODEL, 0);
    rope_kernel<<<32768, 256>>>(qkv);
    attn_mma_kernel<<<dim3(8, 512), 128>>>(qkv, oh);
    hgemm<<<g512, 256>>>(oh, WoT, bo, x, nullptr, hp, MROWS, DMODEL, DMODEL, 0);
    ln_kernel<<<MROWS, 256>>>(hp, ln3g, ln3b, hn);
    hgemm<<<gffn, 256>>>(hn, W1T, b1, nullptr, ffh, nullptr, MROWS, FFND, DMODEL, 1);
    hgemm<<<g512, 256>>>(ffh, W2T, b2, hp, nullptr, out, MROWS, DMODEL, FFND, 0);
}

// round 7
// speedup vs baseline: 5.8672x; 1.0887x over previous
#include <cuda_runtime.h>
#include <cuda_fp16.h>
#include <math.h>
#include <stdint.h>

#define MROWS 32768
#define DMODEL 512
#define FFND 2048
#define SAPAD 40    // halfs per smem row in GEMM (32 data + 8 pad)
#define ATP 72      // half pitch of 64-wide attention smem tiles
#define STGB 20480  // bytes per hgemm pipeline stage (A 10240 + B 10240)
#define KVB 9216    // bytes per 64x64 half tile with ATP pitch (64*72*2)

// ---------------- scratch ----------------
__device__ __half g_hn [(size_t)MROWS * DMODEL];
__device__ __half g_qkv[(size_t)MROWS * 1536];
__device__ __half g_oh [(size_t)MROWS * DMODEL];
__device__ float  g_h  [(size_t)MROWS * DMODEL];
__device__ __half g_ffh[(size_t)MROWS * FFND];
__device__ __half g_wTh[512 * 1536 + 512 * 512 + 512 * 2048 + 2048 * 512];
__device__ float  g_bqkv[1536];

__device__ __forceinline__ uint32_t smem_u32(const void* p) {
    uint32_t a;
    asm("{ .reg .u64 t; cvta.to.shared.u64 t, %1; cvt.u32.u64 %0, t; }" : "=r"(a) : "l"(p));
    return a;
}
__device__ __forceinline__ uint32_t pack_h2(float a, float b) {
    __half2 h = __floats2half2_rn(a, b);
    return *reinterpret_cast<uint32_t*>(&h);
}

#define LDMX4(r, addr) \
    asm volatile("ldmatrix.sync.aligned.m8n8.x4.shared.b16 {%0,%1,%2,%3}, [%4];" \
        : "=r"((r)[0]), "=r"((r)[1]), "=r"((r)[2]), "=r"((r)[3]) : "r"(addr))
#define LDMX4T(r, addr) \
    asm volatile("ldmatrix.sync.aligned.m8n8.x4.trans.shared.b16 {%0,%1,%2,%3}, [%4];" \
        : "=r"((r)[0]), "=r"((r)[1]), "=r"((r)[2]), "=r"((r)[3]) : "r"(addr))
#define MMA16816(c, a, b0, b1) \
    asm volatile("mma.sync.aligned.m16n8k16.row.col.f32.f16.f16.f32 " \
        "{%0,%1,%2,%3}, {%4,%5,%6,%7}, {%8,%9}, {%0,%1,%2,%3};" \
        : "+f"((c)[0]), "+f"((c)[1]), "+f"((c)[2]), "+f"((c)[3]) \
        : "r"((a)[0]), "r"((a)[1]), "r"((a)[2]), "r"((a)[3]), "r"(b0), "r"(b1))
#define CPASYNC16(dst, src) \
    asm volatile("cp.async.cg.shared.global [%0], [%1], 16;" :: "r"(dst), "l"(src))
#define CPCOMMIT() asm volatile("cp.async.commit_group;" ::: "memory")
#define CPWAIT(n)  asm volatile("cp.async.wait_group %0;" :: "n"(n) : "memory")

// ---------------- weight transpose + fp16 convert (R x C -> C x R) ----------------
__global__ void transpose_h(const float* __restrict__ in, __half* __restrict__ out,
                            int R, int C) {
    __shared__ float t[32][33];
    int bc = blockIdx.x * 32, br = blockIdx.y * 32;
    int x = threadIdx.x, y = threadIdx.y;
    #pragma unroll
    for (int i = 0; i < 32; i += 8)
        t[y + i][x] = in[(size_t)(br + y + i) * C + bc + x];
    __syncthreads();
    #pragma unroll
    for (int i = 0; i < 32; i += 8)
        out[(size_t)(bc + y + i) * R + br + x] = __float2half_rn(t[x][y + i]);
}

__global__ void concat_bias(const float* __restrict__ bq, const float* __restrict__ bk,
                            const float* __restrict__ bv, float* __restrict__ o) {
    int i = blockIdx.x * 256 + threadIdx.x;
    o[i] = i < 512 ? bq[i] : (i < 1024 ? bk[i - 512] : bv[i - 1024]);
}

// ---------------- LayerNorm: fp32 in, fp16 out ----------------
__global__ void ln_kernel(const float* __restrict__ x, const float* __restrict__ g,
                          const float* __restrict__ b, __half* __restrict__ y) {
    int row = blockIdx.x;
    int tid = threadIdx.x;
    const float2* xr = (const float2*)(x + (size_t)row * DMODEL);
    float2 v = xr[tid];
    float s  = v.x + v.y;
    float ss = v.x * v.x + v.y * v.y;
    #pragma unroll
    for (int o = 16; o > 0; o >>= 1) {
        s  += __shfl_xor_sync(0xffffffffu, s,  o);
        ss += __shfl_xor_sync(0xffffffffu, ss, o);
    }
    __shared__ float sh[16];
    int w = tid >> 5, lane = tid & 31;
    if (lane == 0) { sh[w] = s; sh[8 + w] = ss; }
    __syncthreads();
    if (tid == 0) {
        float ts = 0.f, tss = 0.f;
        #pragma unroll
        for (int i = 0; i < 8; i++) { ts += sh[i]; tss += sh[8 + i]; }
        sh[0] = ts; sh[8] = tss;
    }
    __syncthreads();
    float mean = sh[0] * (1.0f / DMODEL);
    float var  = sh[8] * (1.0f / DMODEL) - mean * mean;
    float rstd = rsqrtf(var + 1e-5f);
    float2 gg = ((const float2*)g)[tid];
    float2 bb = ((const float2*)b)[tid];
    ((__half2*)(y + (size_t)row * DMODEL))[tid] =
        __floats2half2_rn((v.x - mean) * rstd * gg.x + bb.x,
                          (v.y - mean) * rstd * gg.y + bb.y);
}

// ---------------- HMMA fp16 GEMM: out = epi(A[MxK] @ Bt[NxK]^T + bias) ----------------
// 4-stage cp.async ring, single barrier per 32-K chunk.
#define HG_ISSUE(chnk) do { \
    uint32_t d = sA0 + (uint32_t)(((chnk) & 3) * STGB); \
    const __half* ga = ga0 + ((chnk) << 5); \
    const __half* gb = gb0 + ((chnk) << 5); \
    CPASYNC16(d, ga); CPASYNC16(d + 16, ga + 8); \
    CPASYNC16(d + 10240, gb); CPASYNC16(d + 10240 + 16, gb + 8); \
} while (0)

__global__ __launch_bounds__(256, 2) void hgemm(
    const __half* __restrict__ A, const __half* __restrict__ Bt,
    const float* __restrict__ bias, const float* __restrict__ res,
    __half* __restrict__ Ch, float* __restrict__ Cf,
    int M, int N, int K, int do_gelu)
{
    extern __shared__ __half smd[];   // 4 stages x 10240 halves
    uint32_t smb = smem_u32(smd);

    int tid = threadIdx.x;
    int wid = tid >> 5, lane = tid & 31;
    int bm = blockIdx.y * 128, bn = blockIdx.x * 128;
    int wm = (wid >> 2) * 64, wn = (wid & 3) * 32;

    const __half* Ab = A  + (size_t)bm * K;
    const __half* Bb = Bt + (size_t)bn * K;

    int lrow = tid >> 1;
    int lko  = (tid & 1) * 16;
    uint32_t sA0 = smb + (uint32_t)(lrow * SAPAD + lko) * 2;
    const __half* ga0 = Ab + (size_t)lrow * K + lko;
    const __half* gb0 = Bb + (size_t)lrow * K + lko;

    uint32_t a_lrow = (uint32_t)(wm + (lane & 15));
    uint32_t a_lk   = (uint32_t)((lane >> 4) * 8);
    uint32_t b_lrow = (uint32_t)(wn + ((lane >> 4) << 3) + (lane & 7));
    uint32_t b_lk   = (uint32_t)(((lane >> 3) & 1) * 8);

    float acc[4][4][4];
    #pragma unroll
    for (int i = 0; i < 4; i++)
        #pragma unroll
        for (int j = 0; j < 4; j++)
            #pragma unroll
            for (int c = 0; c < 4; c++) acc[i][j][c] = 0.f;

    int nch = K >> 5;
    HG_ISSUE(0); CPCOMMIT();
    HG_ISSUE(1); CPCOMMIT();
    HG_ISSUE(2); CPCOMMIT();

    for (int ch = 0; ch < nch; ch++) {
        CPWAIT(2);
        __syncthreads();
        int np = ch + 3;
        if (np < nch) HG_ISSUE(np);
        CPCOMMIT();

        uint32_t abase = smb + (uint32_t)((ch & 3) * STGB);
        uint32_t bbase = abase + 10240u;
        #pragma unroll
        for (int ks = 0; ks < 2; ks++) {
            uint32_t kb = (uint32_t)(ks << 4);
            uint32_t afr[4][4], bfr[2][4];
            #pragma unroll
            for (int mi = 0; mi < 4; mi++) {
                uint32_t addr = abase + ((a_lrow + mi * 16) * SAPAD + kb + a_lk) * 2;
                LDMX4(afr[mi], addr);
            }
            #pragma unroll
            for (int nh = 0; nh < 2; nh++) {
                uint32_t addr = bbase + ((b_lrow + nh * 16) * SAPAD + kb + b_lk) * 2;
                LDMX4(bfr[nh], addr);
            }
            #pragma unroll
            for (int mi = 0; mi < 4; mi++)
                #pragma unroll
                for (int nj = 0; nj < 4; nj++) {
                    uint32_t b0 = bfr[nj >> 1][(nj & 1) * 2];
                    uint32_t b1 = bfr[nj >> 1][(nj & 1) * 2 + 1];
                    MMA16816(acc[mi][nj], afr[mi], b0, b1);
                }
        }
    }

    int g4 = lane >> 2, tc = (lane & 3) * 2;
    #pragma unroll
    for (int mi = 0; mi < 4; mi++) {
        #pragma unroll
        for (int r = 0; r < 2; r++) {
            size_t row = (size_t)(bm + wm + mi * 16 + g4 + r * 8);
            #pragma unroll
            for (int nj = 0; nj < 4; nj++) {
                int col = bn + wn + nj * 8 + tc;
                float v0 = acc[mi][nj][r * 2]     + bias[col];
                float v1 = acc[mi][nj][r * 2 + 1] + bias[col + 1];
                if (do_gelu) {
                    v0 = 0.5f * v0 * (1.0f + erff(v0 * 0.7071067811865475f));
                    v1 = 0.5f * v1 * (1.0f + erff(v1 * 0.7071067811865475f));
                }
                if (Ch) {
                    *(__half2*)(Ch + row * (size_t)N + col) = __floats2half2_rn(v0, v1);
                } else {
                    if (res) {
                        float2 rv = *(const float2*)(res + row * (size_t)N + col);
                        v0 += rv.x; v1 += rv.y;
                    }
                    float2 o2; o2.x = v0; o2.y = v1;
                    *(float2*)(Cf + row * (size_t)N + col) = o2;
                }
            }
        }
    }
}

// ---------------- RoPE (in-place on packed qkv, half) ----------------
__global__ void rope_kernel(__half* __restrict__ qkv) {
    int i = blockIdx.x * 256 + threadIdx.x;
    int j   = i & 15;
    int h   = (i >> 4) & 7;
    int row = (i >> 7) & (MROWS - 1);
    int isk = (i >> 22) & 1;
    int s = row & 511;
    float ang = (float)s * __expf(-(float)j * 0.28782313662425575f);
    float sn, cs;
    sincosf(ang, &sn, &cs);
    __half* p = qkv + (size_t)row * 1536 + isk * 512 + h * 64 + j;
    float x1 = __half2float(p[0]), x2 = __half2float(p[32]);
    p[0]  = __float2half_rn(x1 * cs - x2 * sn);
    p[32] = __float2half_rn(x2 * cs + x1 * sn);
}

// ---------------- HMMA flash attention (half qkv in, half o out) ----------------
// Single shared array: Q @ 0, K bufs @ KVB,2*KVB, V bufs @ 3*KVB,4*KVB (bytes).
#define AT_ISSUE(kt) do { \
    uint32_t _kd = smb + (uint32_t)(KVB + ((kt) & 1) * KVB); \
    uint32_t _vd = smb + (uint32_t)(3 * KVB + ((kt) & 1) * KVB); \
    _Pragma("unroll") \
    for (int _l = 0; _l < 4; _l++) { \
        int _f = tid + _l * 128; \
        int _r = _f >> 3, _c8 = (_f & 7) << 3; \
        CPASYNC16(_kd + (uint32_t)(_r * ATP + _c8) * 2, \
                  kb + (size_t)((kt) * 64 + _r) * 1536 + _c8); \
        CPASYNC16(_vd + (uint32_t)(_r * ATP + _c8) * 2, \
                  vb + (size_t)((kt) * 64 + _r) * 1536 + _c8); \
    } \
} while (0)

__global__ __launch_bounds__(128) void attn_mma_kernel(
    const __half* __restrict__ qkv, __half* __restrict__ o)
{
    __shared__ __half smatt[5 * 64 * ATP];   // Q + 2K + 2V
    uint32_t smb = smem_u32(smatt);

    int qt = blockIdx.x, bch = blockIdx.y;
    int bc = bch >> 3, h = bch & 7;
    int tid = threadIdx.x;
    int w = tid >> 5, lane = tid & 31;
    int g = lane >> 2, t = lane & 3;

    const __half* qb = qkv + (size_t)(bc * 512 + qt * 64) * 1536 + h * 64;
    const __half* kb = qkv + (size_t)(bc * 512) * 1536 + 512 + h * 64;
    const __half* vb = qkv + (size_t)(bc * 512) * 1536 + 1024 + h * 64;

    AT_ISSUE(0);
    CPCOMMIT();

    #pragma unroll
    for (int l = 0; l < 4; l++) {
        int f = tid + l * 128;
        int r = f >> 3, c8 = (f & 7) << 3;
        *(uint4*)&smatt[r * ATP + c8] = *(const uint4*)(qb + (size_t)r * 1536 + c8);
    }
    __syncthreads();

    uint32_t qf[4][4];
    {
        uint32_t arow = (uint32_t)(16 * w + (lane & 15));
        uint32_t akof = (uint32_t)((lane >> 4) << 3);
        #pragma unroll
        for (int ks = 0; ks < 4; ks++) {
            uint32_t addr = smb + ((arow * ATP + (ks << 4) + akof) << 1);
            LDMX4(qf[ks], addr);
        }
    }

    float m0 = -1e30f, m1 = -1e30f, l0 = 0.f, l1 = 0.f;
    float of[8][4];
    #pragma unroll
    for (int nj = 0; nj < 8; nj++)
        #pragma unroll
        for (int c = 0; c < 4; c++) of[nj][c] = 0.f;

    uint32_t kb_row = (uint32_t)(((lane >> 4) << 3) + (lane & 7));
    uint32_t kb_kof = (uint32_t)(((lane >> 3) & 1) << 3);
    uint32_t vb_row = (uint32_t)((((lane >> 3) & 1) << 3) + (lane & 7));
    uint32_t vb_cof = (uint32_t)((lane >> 4) << 3);

    for (int kt = 0; kt < 8; kt++) {
        CPWAIT(0);
        __syncthreads();
        if (kt + 1 < 8) AT_ISSUE(kt + 1);
        CPCOMMIT();

        uint32_t kbase = smb + (uint32_t)(KVB + (kt & 1) * KVB);
        uint32_t vbase = smb + (uint32_t)(3 * KVB + (kt & 1) * KVB);

        // S = (Q @ K^T) * 0.125
        float sf[8][4];
        #pragma unroll
        for (int nj = 0; nj < 8; nj++)
            #pragma unroll
            for (int c = 0; c < 4; c++) sf[nj][c] = 0.f;
        #pragma unroll
        for (int ks = 0; ks < 4; ks++) {
            #pragma unroll
            for (int nh = 0; nh < 4; nh++) {
                uint32_t addr = kbase + ((((nh << 4) + kb_row) * ATP + (ks << 4) + kb_kof) << 1);
                uint32_t kf[4];
                LDMX4(kf, addr);
                MMA16816(sf[2 * nh],     qf[ks], kf[0], kf[1]);
                MMA16816(sf[2 * nh + 1], qf[ks], kf[2], kf[3]);
            }
        }
        #pragma unroll
        for (int nj = 0; nj < 8; nj++)
            #pragma unroll
            for (int c = 0; c < 4; c++) sf[nj][c] *= 0.125f;

        // online softmax (rows g and g+8)
        float rm0 = -1e30f, rm1 = -1e30f;
        #pragma unroll
        for (int nj = 0; nj < 8; nj++) {
            rm0 = fmaxf(rm0, fmaxf(sf[nj][0], sf[nj][1]));
            rm1 = fmaxf(rm1, fmaxf(sf[nj][2], sf[nj][3]));
        }
        #pragma unroll
        for (int off = 1; off <= 2; off <<= 1) {
            rm0 = fmaxf(rm0, __shfl_xor_sync(0xffffffffu, rm0, off));
            rm1 = fmaxf(rm1, __shfl_xor_sync(0xffffffffu, rm1, off));
        }
        float mn0 = fmaxf(m0, rm0), mn1 = fmaxf(m1, rm1);
        float cr0 = __expf(m0 - mn0), cr1 = __expf(m1 - mn1);
        float rs0 = 0.f, rs1 = 0.f;
        #pragma unroll
        for (int nj = 0; nj < 8; nj++) {
            sf[nj][0] = __expf(sf[nj][0] - mn0);
            sf[nj][1] = __expf(sf[nj][1] - mn0);
            sf[nj][2] = __expf(sf[nj][2] - mn1);
            sf[nj][3] = __expf(sf[nj][3] - mn1);
            rs0 += sf[nj][0] + sf[nj][1];
            rs1 += sf[nj][2] + sf[nj][3];
        }
        #pragma unroll
        for (int off = 1; off <= 2; off <<= 1) {
            rs0 += __shfl_xor_sync(0xffffffffu, rs0, off);
            rs1 += __shfl_xor_sync(0xffffffffu, rs1, off);
        }
        l0 = l0 * cr0 + rs0;
        l1 = l1 * cr1 + rs1;
        m0 = mn0; m1 = mn1;
        #pragma unroll
        for (int nj = 0; nj < 8; nj++) {
            of[nj][0] *= cr0; of[nj][1] *= cr0;
            of[nj][2] *= cr1; of[nj][3] *= cr1;
        }

        uint32_t pf[4][4];
        #pragma unroll
        for (int ks = 0; ks < 4; ks++) {
            pf[ks][0] = pack_h2(sf[2 * ks][0],     sf[2 * ks][1]);
            pf[ks][1] = pack_h2(sf[2 * ks][2],     sf[2 * ks][3]);
            pf[ks][2] = pack_h2(sf[2 * ks + 1][0], sf[2 * ks + 1][1]);
            pf[ks][3] = pack_h2(sf[2 * ks + 1][2], sf[2 * ks + 1][3]);
        }

        #pragma unroll
        for (int ks = 0; ks < 4; ks++) {
            #pragma unroll
            for (int nh = 0; nh < 4; nh++) {
                uint32_t addr = vbase + ((((ks << 4) + vb_row) * ATP + (nh << 4) + vb_cof) << 1);
                uint32_t vf[4];
                LDMX4T(vf, addr);
                MMA16816(of[2 * nh],     pf[ks], vf[0], vf[1]);
                MMA16816(of[2 * nh + 1], pf[ks], vf[2], vf[3]);
            }
        }
    }

    __half* ob = o + (size_t)(bc * 512 + qt * 64) * 512 + h * 64;
    float inv0 = 1.0f / l0, inv1 = 1.0f / l1;
    #pragma unroll
    for (int nj = 0; nj < 8; nj++) {
        int col = nj * 8 + t * 2;
        *(__half2*)(ob + (size_t)(16 * w + g) * 512 + col) =
            __floats2half2_rn(of[nj][0] * inv0, of[nj][1] * inv0);
        *(__half2*)(ob + (size_t)(16 * w + g + 8) * 512 + col) =
            __floats2half2_rn(of[nj][2] * inv1, of[nj][3] * inv1);
    }
}

// ---------------- launch ----------------
extern "C" void kernel_launch(void* const* d_in, const int* in_sizes, int n_in,
                              void* d_out, int out_size) {
    const float* x    = (const float*)d_in[0];
    const float* Wq   = (const float*)d_in[1];
    const float* bq   = (const float*)d_in[2];
    const float* Wk   = (const float*)d_in[3];
    const float* bk   = (const float*)d_in[4];
    const float* Wv   = (const float*)d_in[5];
    const float* bv   = (const float*)d_in[6];
    const float* Wo   = (const float*)d_in[7];
    const float* bo   = (const float*)d_in[8];
    const float* ln1g = (const float*)d_in[9];
    const float* ln1b = (const float*)d_in[10];
    const float* ln3g = (const float*)d_in[11];
    const float* ln3b = (const float*)d_in[12];
    const float* W1   = (const float*)d_in[13];
    const float* b1   = (const float*)d_in[14];
    const float* W2   = (const float*)d_in[15];
    const float* b2   = (const float*)d_in[16];
    float* out = (float*)d_out;

    __half *hn, *qkv, *oh, *ffh, *wth;
    float *hp, *bqkv;
    cudaGetSymbolAddress((void**)&hn,   g_hn);
    cudaGetSymbolAddress((void**)&qkv,  g_qkv);
    cudaGetSymbolAddress((void**)&oh,   g_oh);
    cudaGetSymbolAddress((void**)&hp,   g_h);
    cudaGetSymbolAddress((void**)&ffh,  g_ffh);
    cudaGetSymbolAddress((void**)&wth,  g_wTh);
    cudaGetSymbolAddress((void**)&bqkv, g_bqkv);

    __half* WqkvT = wth;                       // [1536][512]
    __half* WoT   = wth + 512 * 1536;          // [512][512]
    __half* W1T   = WoT + 512 * 512;           // [2048][512]
    __half* W2T   = W1T + 512 * 2048;          // [512][2048]

    const int smemG = 4 * STGB;   // 81920
    cudaFuncSetAttribute(hgemm, cudaFuncAttributeMaxDynamicSharedMemorySize, smemG);

    dim3 tb(32, 8);
    transpose_h<<<dim3(16, 16), tb>>>(Wq, WqkvT,              512, 512);
    transpose_h<<<dim3(16, 16), tb>>>(Wk, WqkvT + 512 * 512,  512, 512);
    transpose_h<<<dim3(16, 16), tb>>>(Wv, WqkvT + 1024 * 512, 512, 512);
    transpose_h<<<dim3(16, 16), tb>>>(Wo, WoT, 512, 512);
    transpose_h<<<dim3(64, 16), tb>>>(W1, W1T, 512, 2048);
    transpose_h<<<dim3(16, 64), tb>>>(W2, W2T, 2048, 512);
    concat_bias<<<6, 256>>>(bq, bk, bv, bqkv);

    dim3 g512(4, MROWS / 128);
    dim3 gqkv(12, MROWS / 128);
    dim3 gffn(16, MROWS / 128);

    ln_kernel<<<MROWS, 256>>>(x, ln1g, ln1b, hn);
    hgemm<<<gqkv, 256, smemG>>>(hn, WqkvT, bqkv, nullptr, qkv, nullptr, MROWS, 1536, DMODEL, 0);
    rope_kernel<<<32768, 256>>>(qkv);
    attn_mma_kernel<<<dim3(8, 512), 128>>>(qkv, oh);
    hgemm<<<g512, 256, smemG>>>(oh, WoT, bo, x, nullptr, hp, MROWS, DMODEL, DMODEL, 0);
    ln_kernel<<<MROWS, 256>>>(hp, ln3g, ln3b, hn);
    hgemm<<<gffn, 256, smemG>>>(hn, W1T, b1, nullptr, ffh, nullptr, MROWS, FFND, DMODEL, 1);
    hgemm<<<g512, 256, smemG>>>(ffh, W2T, b2, hp, nullptr, out, MROWS, DMODEL, FFND, 0);
}